// round 2
// baseline (speedup 1.0000x reference)
#include <cuda_runtime.h>
#include <math.h>

#define BB 16
#define HH 512
#define WW 512
#define HWL (HH*WW)
#define NTOT (BB*HWL)
#define NCAND 4096          // (512/8)*(512/8) blocks per image
#define NTOP 500

// ---------------- scratch (device globals; no allocations) ----------------
__device__ float g_gray[NTOT];
__device__ float g_dx2[NTOT];
__device__ float g_dy2[NTOT];
__device__ float g_dxy[NTOT];
__device__ float g_t0[NTOT];
__device__ float g_t1[NTOT];
__device__ float g_t2[NTOT];
__device__ float g_S[NTOT];
__device__ float g_mask[NTOT];
__device__ float g_ctmp[NTOT];
__device__ float g_cor[NTOT];
__device__ float g_box[NTOT];
__device__ float g_cval[BB * NCAND];
__device__ int   g_cidx[BB * NCAND];
__device__ double g_acc[2];

// gaussian(7, sigma=1) 1D weights (normalized)
__constant__ float GW[7] = {0.004433048f, 0.054005582f, 0.242036223f, 0.399050277f,
                            0.242036223f, 0.054005582f, 0.004433048f};

__device__ __forceinline__ int refl(int t, int n) {   // reflect101 ('reflect')
    if (t < 0) t = -t;
    if (t >= n) t = 2 * n - 2 - t;
    return t;
}

// ---------------- 1. gray + zero mask/acc ----------------
__global__ void k_gray(const float* __restrict__ imgs) {
    int idx = blockIdx.x * blockDim.x + threadIdx.x;
    if (idx >= NTOT) return;
    int b = idx / HWL, pix = idx % HWL;
    const float* base = imgs + (size_t)b * 3 * HWL;
    float r = base[pix], g = base[HWL + pix], bl = base[2 * HWL + pix];
    g_gray[idx] = 0.299f * r + 0.587f * g + 0.114f * bl;
    g_mask[idx] = 0.0f;
    if (idx < 2) g_acc[idx] = 0.0;
}

// ---------------- 2. sobel (replicate pad), products ----------------
__global__ void k_sobel() {
    int idx = blockIdx.x * blockDim.x + threadIdx.x;
    if (idx >= NTOT) return;
    int b = idx / HWL, pix = idx % HWL, i = pix / WW, j = pix % WW;
    const float* G = g_gray + (size_t)b * HWL;
    int im = max(i - 1, 0), ip = min(i + 1, HH - 1);
    int jm = max(j - 1, 0), jp = min(j + 1, WW - 1);
    float a  = G[im * WW + jm], b2 = G[im * WW + j], c  = G[im * WW + jp];
    float d  = G[i  * WW + jm],                      f  = G[i  * WW + jp];
    float g2 = G[ip * WW + jm], h2 = G[ip * WW + j], k2 = G[ip * WW + jp];
    float dx = (c  - a + 2.0f * (f  - d ) + k2 - g2) * 0.125f;
    float dy = (g2 - a + 2.0f * (h2 - b2) + k2 - c ) * 0.125f;
    g_dx2[idx] = dx * dx;
    g_dy2[idx] = dy * dy;
    g_dxy[idx] = dx * dy;
}

// ---------------- 3. horizontal gauss7 on 3 channels (reflect) ----------------
__global__ void k_blurH3() {
    int idx = blockIdx.x * blockDim.x + threadIdx.x;
    if (idx >= NTOT) return;
    int b = idx / HWL, pix = idx % HWL, i = pix / WW, j = pix % WW;
    int base = b * HWL + i * WW;
    float s0 = 0.f, s1 = 0.f, s2 = 0.f;
#pragma unroll
    for (int d = -3; d <= 3; d++) {
        int jj = j + d;
        if (jj < 0) jj = -jj; else if (jj >= WW) jj = 2 * WW - 2 - jj;
        float w = GW[d + 3];
        s0 += w * g_dx2[base + jj];
        s1 += w * g_dy2[base + jj];
        s2 += w * g_dxy[base + jj];
    }
    g_t0[idx] = s0; g_t1[idx] = s1; g_t2[idx] = s2;
}

// ---------------- 4. vertical gauss7 + GFTT response ----------------
__global__ void k_blurV3resp() {
    int idx = blockIdx.x * blockDim.x + threadIdx.x;
    if (idx >= NTOT) return;
    int b = idx / HWL, pix = idx % HWL, i = pix / WW, j = pix % WW;
    float a = 0.f, c = 0.f, e = 0.f;
#pragma unroll
    for (int d = -3; d <= 3; d++) {
        int ii = i + d;
        if (ii < 0) ii = -ii; else if (ii >= HH) ii = 2 * HH - 2 - ii;
        int off = b * HWL + ii * WW + j;
        float w = GW[d + 3];
        a += w * g_t0[off];
        c += w * g_t1[off];
        e += w * g_t2[off];
    }
    float det = a * c - e * e;
    float tr = a + c;
    g_S[idx] = 0.5f * (tr - sqrtf(fabsf(tr * tr - 4.0f * det)));
}

// ---------------- 5. 5x5 NMS + per-8x8-block argmax ----------------
__global__ void k_nms() {
    int b = blockIdx.z;
    int i = blockIdx.y * 8 + threadIdx.y;
    int j = blockIdx.x * 8 + threadIdx.x;
    const float* S = g_S + (size_t)b * HWL;
    float s = S[i * WW + j];
    float m = -INFINITY;
#pragma unroll
    for (int di = -2; di <= 2; di++) {
        int ii = i + di;
        if (ii < 0 || ii >= HH) continue;
#pragma unroll
        for (int dj = -2; dj <= 2; dj++) {
            int jj = j + dj;
            if (jj < 0 || jj >= WW) continue;
            m = fmaxf(m, S[ii * WW + jj]);
        }
    }
    float v = (s == m) ? s : 0.0f;

    __shared__ float sval[64];
    __shared__ int   sidx[64];
    int t = threadIdx.y * 8 + threadIdx.x;
    sval[t] = v;
    sidx[t] = i * WW + j;
    __syncthreads();
#pragma unroll
    for (int off = 32; off > 0; off >>= 1) {
        if (t < off) {
            if (sval[t + off] > sval[t] ||
                (sval[t + off] == sval[t] && sidx[t + off] < sidx[t])) {
                sval[t] = sval[t + off];
                sidx[t] = sidx[t + off];
            }
        }
        __syncthreads();
    }
    if (t == 0) {
        int slot = b * NCAND + blockIdx.y * 64 + blockIdx.x;
        g_cval[slot] = sval[0];
        g_cidx[slot] = sidx[0];
    }
}

// ---------------- 6. per-image top-500 over 4096 candidates ----------------
__global__ void k_topk() {
    int b = blockIdx.x;
    __shared__ float sv[NCAND];
    const float* cv = g_cval + b * NCAND;
    const int*   ci = g_cidx + b * NCAND;
    for (int t = threadIdx.x; t < NCAND; t += blockDim.x) sv[t] = cv[t];
    __syncthreads();
    // bitonic sort ascending
    for (int k = 2; k <= NCAND; k <<= 1) {
        for (int j = k >> 1; j > 0; j >>= 1) {
            for (int t = threadIdx.x; t < NCAND; t += blockDim.x) {
                int ixj = t ^ j;
                if (ixj > t) {
                    bool up = ((t & k) == 0);
                    float a = sv[t], c = sv[ixj];
                    if ((a > c) == up) { sv[t] = c; sv[ixj] = a; }
                }
            }
            __syncthreads();
        }
    }
    float thresh = sv[NCAND - NTOP];   // 500th largest value
    __shared__ int firstGreater;
    __shared__ int eqcnt;
    __shared__ int eqidx[256];
    if (threadIdx.x == 0) { firstGreater = NCAND; eqcnt = 0; }
    __syncthreads();

    if (thresh > 0.0f) {
        for (int t = threadIdx.x; t < NCAND; t += blockDim.x) {
            if (sv[t] > thresh && (t == 0 || sv[t - 1] <= thresh))
                atomicMin(&firstGreater, t);
        }
        __syncthreads();
        int cgt = NCAND - firstGreater;          // count strictly > thresh
        for (int t = threadIdx.x; t < NCAND; t += blockDim.x) {
            float v = cv[t];
            if (v > thresh) {
                g_mask[(size_t)b * HWL + ci[t]] = 1.0f;
            } else if (v == thresh) {
                int p = atomicAdd(&eqcnt, 1);
                if (p < 256) eqidx[p] = ci[t];
            }
        }
        __syncthreads();
        if (threadIdx.x == 0) {
            int need = NTOP - cgt;               // ties: lowest index first
            int n = min(eqcnt, 256);
            for (int s = 0; s < need && s < n; s++) {
                int best = -1, bi = 0x7fffffff;
                for (int q = 0; q < n; q++)
                    if (eqidx[q] >= 0 && eqidx[q] < bi) { bi = eqidx[q]; best = q; }
                if (best < 0) break;
                g_mask[(size_t)b * HWL + eqidx[best]] = 1.0f;
                eqidx[best] = -1;
            }
        }
    } else {
        // fewer than 500 positive candidates: all positives are in top-k
        for (int t = threadIdx.x; t < NCAND; t += blockDim.x) {
            if (cv[t] > 0.0f) g_mask[(size_t)b * HWL + ci[t]] = 1.0f;
        }
    }
}

// ---------------- 7/8. gaussian blur of corner mask (separable, reflect) ----------------
__global__ void k_blurH1() {   // mask -> ctmp
    int idx = blockIdx.x * blockDim.x + threadIdx.x;
    if (idx >= NTOT) return;
    int b = idx / HWL, pix = idx % HWL, i = pix / WW, j = pix % WW;
    int base = b * HWL + i * WW;
    float s = 0.f;
#pragma unroll
    for (int d = -3; d <= 3; d++) {
        int jj = j + d;
        if (jj < 0) jj = -jj; else if (jj >= WW) jj = 2 * WW - 2 - jj;
        s += GW[d + 3] * g_mask[base + jj];
    }
    g_ctmp[idx] = s;
}
__global__ void k_blurV1() {   // ctmp -> cor
    int idx = blockIdx.x * blockDim.x + threadIdx.x;
    if (idx >= NTOT) return;
    int b = idx / HWL, pix = idx % HWL, i = pix / WW, j = pix % WW;
    float s = 0.f;
#pragma unroll
    for (int d = -3; d <= 3; d++) {
        int ii = i + d;
        if (ii < 0) ii = -ii; else if (ii >= HH) ii = 2 * HH - 2 - ii;
        s += GW[d + 3] * g_ctmp[b * HWL + ii * WW + j];
    }
    g_cor[idx] = s;
}

// ---------------- 9. horizontal 5-box sum of scores (reflect) ----------------
__global__ void k_box5h(const float* __restrict__ sc) {
    int idx = blockIdx.x * blockDim.x + threadIdx.x;
    if (idx >= NTOT) return;
    int b = idx / HWL, pix = idx % HWL, i = pix / WW, j = pix % WW;
    int base = b * HWL + i * WW;
    float s = 0.f;
#pragma unroll
    for (int d = -2; d <= 2; d++) {
        int jj = j + d;
        if (jj < 0) jj = -jj; else if (jj >= WW) jj = 2 * WW - 2 - jj;
        s += sc[base + jj];
    }
    g_box[idx] = s;
}

// ---------------- 10. final fused losses + reduction ----------------
__global__ void k_final(const float* __restrict__ sc) {
    double acc_bce = 0.0, acc_reg = 0.0;
    for (int idx = blockIdx.x * blockDim.x + threadIdx.x; idx < NTOT;
         idx += gridDim.x * blockDim.x) {
        int b = idx / HWL, pix = idx % HWL, i = pix / WW, j = pix % WW;
        float p = sc[idx];
        float logp = fmaxf(logf(p), -100.0f);
        float l1m  = fmaxf(log1pf(-p), -100.0f);
        float c = g_cor[idx];
        float bce = -(c * logp + (1.0f - c) * l1m);
        float box = 0.f;
#pragma unroll
        for (int d = -2; d <= 2; d++) {
            int ii = i + d;
            if (ii < 0) ii = -ii; else if (ii >= HH) ii = 2 * HH - 2 - ii;
            box += g_box[b * HWL + ii * WW + j];
        }
        float lap = (box - 25.0f * p) * (1.0f / 48.0f);
        float reg = p * expf(-lap);
        acc_bce += (double)bce;
        acc_reg += (double)reg;
    }
    __shared__ double s1[256], s2[256];
    int t = threadIdx.x;
    s1[t] = acc_bce; s2[t] = acc_reg;
    __syncthreads();
    for (int off = 128; off > 0; off >>= 1) {
        if (t < off) { s1[t] += s1[t + off]; s2[t] += s2[t + off]; }
        __syncthreads();
    }
    if (t == 0) {
        atomicAdd(&g_acc[0], s1[0]);
        atomicAdd(&g_acc[1], s2[0]);
    }
}

__global__ void k_fin(float* __restrict__ out) {
    if (threadIdx.x == 0 && blockIdx.x == 0)
        out[0] = (float)((g_acc[0] + 10.0 * g_acc[1]) / (double)NTOT);
}

// ---------------- launch ----------------
extern "C" void kernel_launch(void* const* d_in, const int* in_sizes, int n_in,
                              void* d_out, int out_size) {
    const float* scores = (const float*)d_in[0];
    const float* imgs   = (const float*)d_in[1];
    if (n_in >= 2 && in_sizes[0] > in_sizes[1]) {   // defensive on input order
        scores = (const float*)d_in[1];
        imgs   = (const float*)d_in[0];
    }
    float* out = (float*)d_out;

    const int TPB = 256;
    const int NB  = (NTOT + TPB - 1) / TPB;

    k_gray<<<NB, TPB>>>(imgs);
    k_sobel<<<NB, TPB>>>();
    k_blurH3<<<NB, TPB>>>();
    k_blurV3resp<<<NB, TPB>>>();
    dim3 nmsGrid(WW / 8, HH / 8, BB);
    dim3 nmsBlk(8, 8);
    k_nms<<<nmsGrid, nmsBlk>>>();
    k_topk<<<BB, 512>>>();
    k_blurH1<<<NB, TPB>>>();
    k_blurV1<<<NB, TPB>>>();
    k_box5h<<<NB, TPB>>>(scores);
    k_final<<<1024, 256>>>(scores);
    k_fin<<<1, 32>>>(out);
    (void)out_size;
}

// round 3
// speedup vs baseline: 1.0296x; 1.0296x over previous
#include <cuda_runtime.h>
#include <math.h>

#define BB 16
#define HH 512
#define WW 512
#define HWL (HH*WW)
#define NTOT (BB*HWL)
#define NCAND 4096
#define NTOP 500
#define NTILE 4096   // 16 imgs * 16 * 16 tiles

// ------------- device scratch (no allocations) -------------
__device__ float  g_cval[BB*NCAND];
__device__ int    g_cidx[BB*NCAND];
__device__ int    g_pts[BB*NTOP];
__device__ int    g_npt[BB];
__device__ double g_pA[NTILE];    // dense bce partials
__device__ double g_pB[NTILE];    // reg partials
__device__ double g_accS;         // sparse bce accumulator

// gaussian(7, sigma=1) normalized
__constant__ float GW[7] = {0.004433048f, 0.054005582f, 0.242036223f, 0.399050277f,
                            0.242036223f, 0.054005582f, 0.004433048f};

__device__ __forceinline__ int refl(int t, int n) {   // reflect101
    if (t < 0) t = -t;
    if (t >= n) t = 2 * n - 2 - t;
    return t;
}

// =====================================================================
// Kernel 1: fused gray -> sobel -> structure tensor -> gauss7 blur ->
//           GFTT response -> 5x5 NMS -> per-8x8-block argmax
// tile: 32x32 output; gray tile 44x44; products 42x42; blurH 42x36; S 36x36
// =====================================================================
__global__ void __launch_bounds__(1024) k_gftt(const float* __restrict__ imgs) {
    __shared__ float sm[11140];
    float* P0 = sm;                 // 1764
    float* P1 = sm + 1764;
    float* P2 = sm + 3528;          // ..5292
    float* GR = sm + 5292;          // 1936 (gray) — overwritten by BH later
    float* B0 = sm + 5292;          // 1512 each
    float* B1 = sm + 5292 + 1512;
    float* B2 = sm + 5292 + 3024;   // ..9828
    float* SS = sm + 9828;          // 1296 ..11124
    float* RM = sm;                 // rowmax 1152 (P dead by then)
    float* PVv = sm + 1152;         // 128
    int*   PIi = (int*)(sm + 1280); // 128

    int b  = blockIdx.z;
    int i0 = blockIdx.y * 32, j0 = blockIdx.x * 32;
    int tx = threadIdx.x, ty = threadIdx.y;
    int t  = ty * 32 + tx;
    if (b == 0 && blockIdx.x == 0 && blockIdx.y == 0 && t == 0) g_accS = 0.0;

    const float* img = imgs + (size_t)b * 3 * HWL;

    // --- gray 44x44 (clamped coords; covers replicate pad for sobel) ---
    for (int idx = t; idx < 44*44; idx += 1024) {
        int a = idx / 44, c = idx % 44;
        int gi = min(max(i0 - 6 + a, 0), HH - 1);
        int gj = min(max(j0 - 6 + c, 0), WW - 1);
        int p = gi * WW + gj;
        GR[idx] = 0.299f*img[p] + 0.587f*img[HWL+p] + 0.114f*img[2*HWL+p];
    }
    __syncthreads();

    // --- sobel products 42x42 at reflected coords (= reflect-padded products) ---
    for (int idx = t; idx < 42*42; idx += 1024) {
        int pr = idx / 42, pc = idx % 42;
        int r = refl(i0 - 5 + pr, HH);
        int c = refl(j0 - 5 + pc, WW);
        int rm_ = max(r-1,0)    - (i0-6), r0_ = r - (i0-6), rp_ = min(r+1,HH-1) - (i0-6);
        int cm_ = max(c-1,0)    - (j0-6), c0_ = c - (j0-6), cp_ = min(c+1,WW-1) - (j0-6);
        float A = GR[rm_*44+cm_], Bv = GR[rm_*44+c0_], C = GR[rm_*44+cp_];
        float D = GR[r0_*44+cm_],                      F = GR[r0_*44+cp_];
        float G = GR[rp_*44+cm_], H  = GR[rp_*44+c0_], K = GR[rp_*44+cp_];
        float dx = (C - A + 2.f*(F - D) + K - G) * 0.125f;
        float dy = (G - A + 2.f*(H - Bv) + K - C) * 0.125f;
        P0[idx] = dx*dx; P1[idx] = dy*dy; P2[idx] = dx*dy;
    }
    __syncthreads();

    // --- horizontal gauss7 : rows 42, cols 36 (global cols j0-2..j0+33) ---
    for (int idx = t; idx < 42*36; idx += 1024) {
        int r = idx / 36, cc = idx % 36;
        int base = r * 42 + cc;
        float s0 = 0.f, s1 = 0.f, s2 = 0.f;
#pragma unroll
        for (int k = 0; k < 7; k++) {
            float w = GW[k];
            s0 += w * P0[base + k];
            s1 += w * P1[base + k];
            s2 += w * P2[base + k];
        }
        B0[idx] = s0; B1[idx] = s1; B2[idx] = s2;
    }
    __syncthreads();

    // --- vertical gauss7 + response: S 36x36 (rows i0-2..i0+33) ---
    for (int idx = t; idx < 36*36; idx += 1024) {
        int rr = idx / 36, cc = idx % 36;
        float a = 0.f, c = 0.f, e = 0.f;
#pragma unroll
        for (int k = 0; k < 7; k++) {
            float w = GW[k];
            int row = (rr + k) * 36 + cc;
            a += w * B0[row]; c += w * B1[row]; e += w * B2[row];
        }
        int gi = i0 - 2 + rr, gj = j0 - 2 + cc;
        float det = a * c - e * e, tr = a + c;
        float s = 0.5f * (tr - sqrtf(fabsf(tr*tr - 4.f*det)));
        SS[idx] = (gi >= 0 && gi < HH && gj >= 0 && gj < WW) ? s : -INFINITY;
    }
    __syncthreads();

    // --- 5x5 NMS (separable max, -inf outside image) ---
    for (int idx = t; idx < 36*32; idx += 1024) {
        int r = idx / 32, c = idx % 32;
        float m = SS[r*36 + c];
#pragma unroll
        for (int k = 1; k < 5; k++) m = fmaxf(m, SS[r*36 + c + k]);
        RM[idx] = m;
    }
    __syncthreads();

    float s = SS[(ty+2)*36 + tx + 2];
    float m = RM[ty*32 + tx];
#pragma unroll
    for (int k = 1; k < 5; k++) m = fmaxf(m, RM[(ty+k)*32 + tx]);
    float v = (s == m) ? s : 0.f;
    int bi = (i0 + ty) * WW + (j0 + tx);
    float bv = v;
#pragma unroll
    for (int off = 4; off >= 1; off >>= 1) {
        float ov = __shfl_down_sync(0xffffffffu, bv, off, 8);
        int   oi = __shfl_down_sync(0xffffffffu, bi, off, 8);
        if (ov > bv || (ov == bv && oi < bi)) { bv = ov; bi = oi; }
    }
    if ((tx & 7) == 0) { PVv[ty*4 + (tx >> 3)] = bv; PIi[ty*4 + (tx >> 3)] = bi; }
    __syncthreads();
    if (t < 16) {
        int by = t >> 2, bx = t & 3;
        float mv = PVv[(by*8)*4 + bx]; int mi = PIi[(by*8)*4 + bx];
#pragma unroll
        for (int k = 1; k < 8; k++) {
            float pv = PVv[(by*8 + k)*4 + bx]; int pi2 = PIi[(by*8 + k)*4 + bx];
            if (pv > mv || (pv == mv && pi2 < mi)) { mv = pv; mi = pi2; }
        }
        int slot = b * NCAND + (blockIdx.y*4 + by) * 64 + (blockIdx.x*4 + bx);
        g_cval[slot] = mv; g_cidx[slot] = mi;
    }
}

// =====================================================================
// Kernel 2: per-image top-500 over 4096 candidates -> point list
// =====================================================================
__global__ void k_topk() {
    int b = blockIdx.x;
    __shared__ float sv[NCAND];
    __shared__ int cnt, firstGreater, eqcnt;
    __shared__ int eqidx[256];
    const float* cv = g_cval + b * NCAND;
    const int*   ci = g_cidx + b * NCAND;
    for (int t = threadIdx.x; t < NCAND; t += blockDim.x) sv[t] = cv[t];
    if (threadIdx.x == 0) { cnt = 0; firstGreater = NCAND; eqcnt = 0; }
    __syncthreads();
    for (int k = 2; k <= NCAND; k <<= 1)
        for (int j = k >> 1; j > 0; j >>= 1) {
            for (int t = threadIdx.x; t < NCAND; t += blockDim.x) {
                int ixj = t ^ j;
                if (ixj > t) {
                    bool up = ((t & k) == 0);
                    float A = sv[t], C = sv[ixj];
                    if ((A > C) == up) { sv[t] = C; sv[ixj] = A; }
                }
            }
            __syncthreads();
        }
    float thresh = sv[NCAND - NTOP];
    if (thresh > 0.f) {
        for (int t = threadIdx.x; t < NCAND; t += blockDim.x)
            if (sv[t] > thresh && (t == 0 || sv[t-1] <= thresh))
                atomicMin(&firstGreater, t);
        __syncthreads();
        int cgt = NCAND - firstGreater;
        for (int t = threadIdx.x; t < NCAND; t += blockDim.x) {
            float v = cv[t];
            if (v > thresh) {
                int p = atomicAdd(&cnt, 1);
                if (p < NTOP) g_pts[b*NTOP + p] = ci[t];
            } else if (v == thresh) {
                int p = atomicAdd(&eqcnt, 1);
                if (p < 256) eqidx[p] = ci[t];
            }
        }
        __syncthreads();
        if (threadIdx.x == 0) {
            int need = NTOP - cgt;
            int nn = min(eqcnt, 256);
            int base = min(cnt, NTOP);
            int added = 0;
            for (int s2 = 0; s2 < need && added < nn; s2++) {
                int best = -1, bi2 = 0x7fffffff;
                for (int q = 0; q < nn; q++)
                    if (eqidx[q] >= 0 && eqidx[q] < bi2) { bi2 = eqidx[q]; best = q; }
                if (best < 0) break;
                if (base + added < NTOP) g_pts[b*NTOP + base + added] = eqidx[best];
                eqidx[best] = -1;
                added++;
            }
            g_npt[b] = min(base + added, NTOP);
        }
    } else {
        for (int t = threadIdx.x; t < NCAND; t += blockDim.x)
            if (cv[t] > 0.f) {
                int p = atomicAdd(&cnt, 1);
                if (p < NTOP) g_pts[b*NTOP + p] = ci[t];
            }
        __syncthreads();
        if (threadIdx.x == 0) g_npt[b] = min(cnt, NTOP);
    }
}

// =====================================================================
// Kernel 3: dense part — sum(-log1mp) and reg = p*exp(-lap), tiled 32x32
// =====================================================================
__global__ void __launch_bounds__(1024) k_dense(const float* __restrict__ sc) {
    __shared__ float s[36*36];
    __shared__ float h[36*32];
    __shared__ double w1[32], w2[32];
    int b = blockIdx.z, i0 = blockIdx.y * 32, j0 = blockIdx.x * 32;
    int tx = threadIdx.x, ty = threadIdx.y, t = ty*32 + tx;
    const float* P = sc + (size_t)b * HWL;
    for (int idx = t; idx < 36*36; idx += 1024) {
        int a = idx / 36, c = idx % 36;
        s[idx] = P[refl(i0 - 2 + a, HH) * WW + refl(j0 - 2 + c, WW)];
    }
    __syncthreads();
    for (int idx = t; idx < 36*32; idx += 1024) {
        int r = idx / 32, c = idx % 32;
        float x = s[r*36 + c];
#pragma unroll
        for (int k = 1; k < 5; k++) x += s[r*36 + c + k];
        h[idx] = x;
    }
    __syncthreads();
    float p = s[(ty+2)*36 + tx + 2];
    float box = h[ty*32 + tx];
#pragma unroll
    for (int k = 1; k < 5; k++) box += h[(ty+k)*32 + tx];
    float lap = (box - 25.f * p) * (1.f / 48.f);
    double reg = (double)(p * expf(-lap));
    double bce = (double)(-fmaxf(log1pf(-p), -100.f));
    for (int off = 16; off; off >>= 1) {
        bce += __shfl_down_sync(0xffffffffu, bce, off);
        reg += __shfl_down_sync(0xffffffffu, reg, off);
    }
    if ((t & 31) == 0) { w1[t >> 5] = bce; w2[t >> 5] = reg; }
    __syncthreads();
    if (t < 32) {
        bce = w1[t]; reg = w2[t];
        for (int off = 16; off; off >>= 1) {
            bce += __shfl_down_sync(0xffffffffu, bce, off);
            reg += __shfl_down_sync(0xffffffffu, reg, off);
        }
        if (t == 0) {
            int tile = (b * 16 + blockIdx.y) * 16 + blockIdx.x;
            g_pA[tile] = bce; g_pB[tile] = reg;
        }
    }
}

// =====================================================================
// Kernel 4: sparse corner-BCE: sum_p sum_{49} wr*wc*(log1mp - logp)
// =====================================================================
__global__ void k_sparse(const float* __restrict__ sc) {
    int b = blockIdx.y;
    int n = g_npt[b];
    const float* P = sc + (size_t)b * HWL;
    double acc = 0.0;
    for (int q = blockIdx.x * blockDim.x + threadIdx.x; q < n;
         q += gridDim.x * blockDim.x) {
        int pix = g_pts[b*NTOP + q];
        int pi = pix / WW, pj = pix % WW;
        float wr[7], wc[7];
#pragma unroll
        for (int k = 0; k < 7; k++) { wr[k] = 0.f; wc[k] = 0.f; }
#pragma unroll
        for (int dd = -3; dd <= 3; dd++) {
            float w = GW[dd + 3];
            int j = pi - dd; if (j >= 0 && j < HH) wr[j - pi + 3] += w;
            if (pi >= 1 && pi <= 3) { int j2 = -pi - dd; if (j2 >= 0) wr[j2 - pi + 3] += w; }
            if (pi >= HH-4 && pi <= HH-2) { int j3 = 2*HH - 2 - pi - dd; if (j3 < HH) wr[j3 - pi + 3] += w; }
            j = pj - dd; if (j >= 0 && j < WW) wc[j - pj + 3] += w;
            if (pj >= 1 && pj <= 3) { int j2 = -pj - dd; if (j2 >= 0) wc[j2 - pj + 3] += w; }
            if (pj >= WW-4 && pj <= WW-2) { int j3 = 2*WW - 2 - pj - dd; if (j3 < WW) wc[j3 - pj + 3] += w; }
        }
#pragma unroll
        for (int kr = 0; kr < 7; kr++) {
            float wrow = wr[kr];
            if (wrow == 0.f) continue;
            const float* row = P + (pi - 3 + kr) * WW;
#pragma unroll
            for (int kc = 0; kc < 7; kc++) {
                float w = wrow * wc[kc];
                if (w == 0.f) continue;
                float pv = row[pj - 3 + kc];
                float lg = fmaxf(logf(pv), -100.f);
                float l1 = fmaxf(log1pf(-pv), -100.f);
                acc += (double)(w * (l1 - lg));
            }
        }
    }
    __shared__ double wsum[8];
    int lane = threadIdx.x & 31, wid = threadIdx.x >> 5;
    for (int off = 16; off; off >>= 1) acc += __shfl_down_sync(0xffffffffu, acc, off);
    if (lane == 0) wsum[wid] = acc;
    __syncthreads();
    if (threadIdx.x == 0) {
        double s2 = 0;
        for (int k = 0; k < 8; k++) s2 += wsum[k];
        atomicAdd(&g_accS, s2);
    }
}

// =====================================================================
// Kernel 5: final reduce
// =====================================================================
__global__ void k_fin(float* __restrict__ out) {
    double a = 0, r = 0;
    for (int i = threadIdx.x; i < NTILE; i += blockDim.x) { a += g_pA[i]; r += g_pB[i]; }
    __shared__ double sa[256], sr[256];
    sa[threadIdx.x] = a; sr[threadIdx.x] = r;
    __syncthreads();
    for (int off = 128; off; off >>= 1) {
        if (threadIdx.x < off) { sa[threadIdx.x] += sa[threadIdx.x+off]; sr[threadIdx.x] += sr[threadIdx.x+off]; }
        __syncthreads();
    }
    if (threadIdx.x == 0)
        out[0] = (float)(((sa[0] + g_accS) + 10.0 * sr[0]) / (double)NTOT);
}

// =====================================================================
extern "C" void kernel_launch(void* const* d_in, const int* in_sizes, int n_in,
                              void* d_out, int out_size) {
    const float* scores = (const float*)d_in[0];
    const float* imgs   = (const float*)d_in[1];
    if (n_in >= 2 && in_sizes[0] > in_sizes[1]) {
        scores = (const float*)d_in[1];
        imgs   = (const float*)d_in[0];
    }
    float* out = (float*)d_out;

    dim3 tiles(16, 16, BB);
    dim3 blk(32, 32);
    k_gftt<<<tiles, blk>>>(imgs);
    k_topk<<<BB, 512>>>();
    k_dense<<<tiles, blk>>>(scores);
    k_sparse<<<dim3(4, BB), 256>>>(scores);
    k_fin<<<1, 256>>>(out);
    (void)out_size;
}

// round 4
// speedup vs baseline: 1.1630x; 1.1296x over previous
#include <cuda_runtime.h>
#include <math.h>

#define BB 16
#define HH 512
#define WW 512
#define HWL (HH*WW)
#define NTOT (BB*HWL)
#define NCAND 4096
#define NTOP 500
#define NTILE 4096   // 16 imgs * 16 * 16 tiles

// ------------- device scratch (no allocations) -------------
__device__ float  g_cval[BB*NCAND];
__device__ int    g_cidx[BB*NCAND];
__device__ int    g_pts[BB*NTOP];
__device__ int    g_npt[BB];
__device__ double g_pA[NTILE];    // dense bce partials
__device__ double g_pB[NTILE];    // reg partials
__device__ double g_accS;         // sparse bce accumulator

// gaussian(7, sigma=1) normalized
__constant__ float GW[7] = {0.004433048f, 0.054005582f, 0.242036223f, 0.399050277f,
                            0.242036223f, 0.054005582f, 0.004433048f};

__device__ __forceinline__ int refl(int t, int n) {   // reflect101
    if (t < 0) t = -t;
    if (t >= n) t = 2 * n - 2 - t;
    return t;
}

// =====================================================================
// Kernel 1: fused gray -> sobel -> structure tensor -> gauss7 blur ->
//           GFTT response -> 5x5 NMS -> per-8x8-block argmax
// =====================================================================
__global__ void __launch_bounds__(1024) k_gftt(const float* __restrict__ imgs) {
    __shared__ float sm[11140];
    float* P0 = sm;                 // 1764
    float* P1 = sm + 1764;
    float* P2 = sm + 3528;          // ..5292
    float* GR = sm + 5292;          // 1936 (gray) — overwritten by BH later
    float* B0 = sm + 5292;          // 1512 each
    float* B1 = sm + 5292 + 1512;
    float* B2 = sm + 5292 + 3024;   // ..9828
    float* SS = sm + 9828;          // 1296 ..11124
    float* RM = sm;                 // rowmax 1152 (P dead by then)
    float* PVv = sm + 1152;         // 128
    int*   PIi = (int*)(sm + 1280); // 128

    int b  = blockIdx.z;
    int i0 = blockIdx.y * 32, j0 = blockIdx.x * 32;
    int tx = threadIdx.x, ty = threadIdx.y;
    int t  = ty * 32 + tx;
    if (b == 0 && blockIdx.x == 0 && blockIdx.y == 0 && t == 0) g_accS = 0.0;

    const float* img = imgs + (size_t)b * 3 * HWL;

    // --- gray 44x44 (clamped coords; covers replicate pad for sobel) ---
    for (int idx = t; idx < 44*44; idx += 1024) {
        int a = idx / 44, c = idx % 44;
        int gi = min(max(i0 - 6 + a, 0), HH - 1);
        int gj = min(max(j0 - 6 + c, 0), WW - 1);
        int p = gi * WW + gj;
        GR[idx] = 0.299f*img[p] + 0.587f*img[HWL+p] + 0.114f*img[2*HWL+p];
    }
    __syncthreads();

    // --- sobel products 42x42 at reflected coords ---
    for (int idx = t; idx < 42*42; idx += 1024) {
        int pr = idx / 42, pc = idx % 42;
        int r = refl(i0 - 5 + pr, HH);
        int c = refl(j0 - 5 + pc, WW);
        int rm_ = max(r-1,0)    - (i0-6), r0_ = r - (i0-6), rp_ = min(r+1,HH-1) - (i0-6);
        int cm_ = max(c-1,0)    - (j0-6), c0_ = c - (j0-6), cp_ = min(c+1,WW-1) - (j0-6);
        float A = GR[rm_*44+cm_], Bv = GR[rm_*44+c0_], C = GR[rm_*44+cp_];
        float D = GR[r0_*44+cm_],                      F = GR[r0_*44+cp_];
        float G = GR[rp_*44+cm_], H  = GR[rp_*44+c0_], K = GR[rp_*44+cp_];
        float dx = (C - A + 2.f*(F - D) + K - G) * 0.125f;
        float dy = (G - A + 2.f*(H - Bv) + K - C) * 0.125f;
        P0[idx] = dx*dx; P1[idx] = dy*dy; P2[idx] = dx*dy;
    }
    __syncthreads();

    // --- horizontal gauss7 : rows 42, cols 36 ---
    for (int idx = t; idx < 42*36; idx += 1024) {
        int r = idx / 36, cc = idx % 36;
        int base = r * 42 + cc;
        float s0 = 0.f, s1 = 0.f, s2 = 0.f;
#pragma unroll
        for (int k = 0; k < 7; k++) {
            float w = GW[k];
            s0 += w * P0[base + k];
            s1 += w * P1[base + k];
            s2 += w * P2[base + k];
        }
        B0[idx] = s0; B1[idx] = s1; B2[idx] = s2;
    }
    __syncthreads();

    // --- vertical gauss7 + response: S 36x36 ---
    for (int idx = t; idx < 36*36; idx += 1024) {
        int rr = idx / 36, cc = idx % 36;
        float a = 0.f, c = 0.f, e = 0.f;
#pragma unroll
        for (int k = 0; k < 7; k++) {
            float w = GW[k];
            int row = (rr + k) * 36 + cc;
            a += w * B0[row]; c += w * B1[row]; e += w * B2[row];
        }
        int gi = i0 - 2 + rr, gj = j0 - 2 + cc;
        float det = a * c - e * e, tr = a + c;
        float s = 0.5f * (tr - sqrtf(fabsf(tr*tr - 4.f*det)));
        SS[idx] = (gi >= 0 && gi < HH && gj >= 0 && gj < WW) ? s : -INFINITY;
    }
    __syncthreads();

    // --- 5x5 NMS (separable max) ---
    for (int idx = t; idx < 36*32; idx += 1024) {
        int r = idx / 32, c = idx % 32;
        float m = SS[r*36 + c];
#pragma unroll
        for (int k = 1; k < 5; k++) m = fmaxf(m, SS[r*36 + c + k]);
        RM[idx] = m;
    }
    __syncthreads();

    float s = SS[(ty+2)*36 + tx + 2];
    float m = RM[ty*32 + tx];
#pragma unroll
    for (int k = 1; k < 5; k++) m = fmaxf(m, RM[(ty+k)*32 + tx]);
    float v = (s == m) ? s : 0.f;
    int bi = (i0 + ty) * WW + (j0 + tx);
    float bv = v;
#pragma unroll
    for (int off = 4; off >= 1; off >>= 1) {
        float ov = __shfl_down_sync(0xffffffffu, bv, off, 8);
        int   oi = __shfl_down_sync(0xffffffffu, bi, off, 8);
        if (ov > bv || (ov == bv && oi < bi)) { bv = ov; bi = oi; }
    }
    if ((tx & 7) == 0) { PVv[ty*4 + (tx >> 3)] = bv; PIi[ty*4 + (tx >> 3)] = bi; }
    __syncthreads();
    if (t < 16) {
        int by = t >> 2, bx = t & 3;
        float mv = PVv[(by*8)*4 + bx]; int mi = PIi[(by*8)*4 + bx];
#pragma unroll
        for (int k = 1; k < 8; k++) {
            float pv = PVv[(by*8 + k)*4 + bx]; int pi2 = PIi[(by*8 + k)*4 + bx];
            if (pv > mv || (pv == mv && pi2 < mi)) { mv = pv; mi = pi2; }
        }
        int slot = b * NCAND + (blockIdx.y*4 + by) * 64 + (blockIdx.x*4 + bx);
        g_cval[slot] = mv; g_cidx[slot] = mi;
    }
}

// =====================================================================
// Kernel 2: per-image top-500 over 4096 candidates -> point list
// =====================================================================
__global__ void __launch_bounds__(1024) k_topk() {
    int b = blockIdx.x;
    __shared__ float sv[NCAND];
    __shared__ int cnt, firstGreater, eqcnt;
    __shared__ int eqidx[256];
    const float* cv = g_cval + b * NCAND;
    const int*   ci = g_cidx + b * NCAND;
    for (int t = threadIdx.x; t < NCAND; t += blockDim.x) sv[t] = cv[t];
    if (threadIdx.x == 0) { cnt = 0; firstGreater = NCAND; eqcnt = 0; }
    __syncthreads();
    for (int k = 2; k <= NCAND; k <<= 1)
        for (int j = k >> 1; j > 0; j >>= 1) {
            for (int t = threadIdx.x; t < NCAND; t += blockDim.x) {
                int ixj = t ^ j;
                if (ixj > t) {
                    bool up = ((t & k) == 0);
                    float A = sv[t], C = sv[ixj];
                    if ((A > C) == up) { sv[t] = C; sv[ixj] = A; }
                }
            }
            __syncthreads();
        }
    float thresh = sv[NCAND - NTOP];
    if (thresh > 0.f) {
        for (int t = threadIdx.x; t < NCAND; t += blockDim.x)
            if (sv[t] > thresh && (t == 0 || sv[t-1] <= thresh))
                atomicMin(&firstGreater, t);
        __syncthreads();
        int cgt = NCAND - firstGreater;
        for (int t = threadIdx.x; t < NCAND; t += blockDim.x) {
            float v = cv[t];
            if (v > thresh) {
                int p = atomicAdd(&cnt, 1);
                if (p < NTOP) g_pts[b*NTOP + p] = ci[t];
            } else if (v == thresh) {
                int p = atomicAdd(&eqcnt, 1);
                if (p < 256) eqidx[p] = ci[t];
            }
        }
        __syncthreads();
        if (threadIdx.x == 0) {
            int need = NTOP - cgt;
            int nn = min(eqcnt, 256);
            int base = min(cnt, NTOP);
            int added = 0;
            for (int s2 = 0; s2 < need && added < nn; s2++) {
                int best = -1, bi2 = 0x7fffffff;
                for (int q = 0; q < nn; q++)
                    if (eqidx[q] >= 0 && eqidx[q] < bi2) { bi2 = eqidx[q]; best = q; }
                if (best < 0) break;
                if (base + added < NTOP) g_pts[b*NTOP + base + added] = eqidx[best];
                eqidx[best] = -1;
                added++;
            }
            g_npt[b] = min(base + added, NTOP);
        }
    } else {
        for (int t = threadIdx.x; t < NCAND; t += blockDim.x)
            if (cv[t] > 0.f) {
                int p = atomicAdd(&cnt, 1);
                if (p < NTOP) g_pts[b*NTOP + p] = ci[t];
            }
        __syncthreads();
        if (threadIdx.x == 0) g_npt[b] = min(cnt, NTOP);
    }
}

// =====================================================================
// Kernel 3: dense part — sum(-log1mp) and reg = p*exp(-lap), tiled 32x32
// =====================================================================
__global__ void __launch_bounds__(1024) k_dense(const float* __restrict__ sc) {
    __shared__ float s[36*36];
    __shared__ float h[36*32];
    __shared__ double w1[32], w2[32];
    int b = blockIdx.z, i0 = blockIdx.y * 32, j0 = blockIdx.x * 32;
    int tx = threadIdx.x, ty = threadIdx.y, t = ty*32 + tx;
    const float* P = sc + (size_t)b * HWL;
    for (int idx = t; idx < 36*36; idx += 1024) {
        int a = idx / 36, c = idx % 36;
        s[idx] = P[refl(i0 - 2 + a, HH) * WW + refl(j0 - 2 + c, WW)];
    }
    __syncthreads();
    for (int idx = t; idx < 36*32; idx += 1024) {
        int r = idx / 32, c = idx % 32;
        float x = s[r*36 + c];
#pragma unroll
        for (int k = 1; k < 5; k++) x += s[r*36 + c + k];
        h[idx] = x;
    }
    __syncthreads();
    float p = s[(ty+2)*36 + tx + 2];
    float box = h[ty*32 + tx];
#pragma unroll
    for (int k = 1; k < 5; k++) box += h[(ty+k)*32 + tx];
    float lap = (box - 25.f * p) * (1.f / 48.f);
    double reg = (double)(p * expf(-lap));
    double bce = (double)(-fmaxf(log1pf(-p), -100.f));
    for (int off = 16; off; off >>= 1) {
        bce += __shfl_down_sync(0xffffffffu, bce, off);
        reg += __shfl_down_sync(0xffffffffu, reg, off);
    }
    if ((t & 31) == 0) { w1[t >> 5] = bce; w2[t >> 5] = reg; }
    __syncthreads();
    if (t < 32) {
        bce = w1[t]; reg = w2[t];
        for (int off = 16; off; off >>= 1) {
            bce += __shfl_down_sync(0xffffffffu, bce, off);
            reg += __shfl_down_sync(0xffffffffu, reg, off);
        }
        if (t == 0) {
            int tile = (b * 16 + blockIdx.y) * 16 + blockIdx.x;
            g_pA[tile] = bce; g_pB[tile] = reg;
        }
    }
}

// =====================================================================
// Kernel 4: sparse corner-BCE, parallel over (point, tap) pairs
//   contribution: wrow(kr)*wcol(kc) * (log1mp - logp) at (pi-3+kr, pj-3+kc)
// =====================================================================
__global__ void k_sparse(const float* __restrict__ sc) {
    int b = blockIdx.y;
    int n = g_npt[b];
    int total = n * 49;
    const float* P = sc + (size_t)b * HWL;
    double acc = 0.0;
    for (int w = blockIdx.x * blockDim.x + threadIdx.x; w < total;
         w += gridDim.x * blockDim.x) {
        int q = w / 49, tap = w % 49;
        int pix = g_pts[b*NTOP + q];
        int pi = pix / WW, pj = pix % WW;
        int kr = tap / 7, kc = tap % 7;
        int R = pi - 3 + kr, C = pj - 3 + kc;
        if (R < 0 || R >= HH || C < 0 || C >= WW) continue;
        // row weight: direct + reflect-folded (reflect101)
        float wrow = GW[kr];
        if (pi >= 1 && pi <= 3) {
            int d = -pi - R;                       // r+d = -pi (low reflection)
            if (d >= -3 && d <= 3) wrow += GW[d+3];
        }
        if (pi >= HH-4 && pi <= HH-2) {
            int d = 2*HH - 2 - pi - R;             // r+d = 2H-2-pi (high reflection)
            if (d >= -3 && d <= 3) wrow += GW[d+3];
        }
        float wcol = GW[kc];
        if (pj >= 1 && pj <= 3) {
            int d = -pj - C;
            if (d >= -3 && d <= 3) wcol += GW[d+3];
        }
        if (pj >= WW-4 && pj <= WW-2) {
            int d = 2*WW - 2 - pj - C;
            if (d >= -3 && d <= 3) wcol += GW[d+3];
        }
        float pv = P[R*WW + C];
        float lg = fmaxf(logf(pv), -100.f);
        float l1 = fmaxf(log1pf(-pv), -100.f);
        acc += (double)((wrow * wcol) * (l1 - lg));
    }
    __shared__ double wsum[8];
    int lane = threadIdx.x & 31, wid = threadIdx.x >> 5;
    for (int off = 16; off; off >>= 1) acc += __shfl_down_sync(0xffffffffu, acc, off);
    if (lane == 0) wsum[wid] = acc;
    __syncthreads();
    if (threadIdx.x == 0) {
        double s2 = 0;
        for (int k = 0; k < 8; k++) s2 += wsum[k];
        atomicAdd(&g_accS, s2);
    }
}

// =====================================================================
// Kernel 5: final reduce
// =====================================================================
__global__ void k_fin(float* __restrict__ out) {
    double a = 0, r = 0;
    for (int i = threadIdx.x; i < NTILE; i += blockDim.x) { a += g_pA[i]; r += g_pB[i]; }
    __shared__ double sa[256], sr[256];
    sa[threadIdx.x] = a; sr[threadIdx.x] = r;
    __syncthreads();
    for (int off = 128; off; off >>= 1) {
        if (threadIdx.x < off) { sa[threadIdx.x] += sa[threadIdx.x+off]; sr[threadIdx.x] += sr[threadIdx.x+off]; }
        __syncthreads();
    }
    if (threadIdx.x == 0)
        out[0] = (float)(((sa[0] + g_accS) + 10.0 * sr[0]) / (double)NTOT);
}

// ---------------- streams/events for fork-join overlap ----------------
struct HxStreams {
    cudaStream_t side;
    cudaEvent_t evFork, evJoin;
    HxStreams() {
        cudaStreamCreateWithFlags(&side, cudaStreamNonBlocking);
        cudaEventCreateWithFlags(&evFork, cudaEventDisableTiming);
        cudaEventCreateWithFlags(&evJoin, cudaEventDisableTiming);
    }
};
static HxStreams g_hx;

// =====================================================================
extern "C" void kernel_launch(void* const* d_in, const int* in_sizes, int n_in,
                              void* d_out, int out_size) {
    const float* scores = (const float*)d_in[0];
    const float* imgs   = (const float*)d_in[1];
    if (n_in >= 2 && in_sizes[0] > in_sizes[1]) {
        scores = (const float*)d_in[1];
        imgs   = (const float*)d_in[0];
    }
    float* out = (float*)d_out;

    dim3 tiles(16, 16, BB);
    dim3 blk(32, 32);

    // fork: dense pass runs concurrently with gftt->topk->sparse chain
    cudaEventRecord(g_hx.evFork, 0);
    cudaStreamWaitEvent(g_hx.side, g_hx.evFork, 0);
    k_dense<<<tiles, blk, 0, g_hx.side>>>(scores);
    cudaEventRecord(g_hx.evJoin, g_hx.side);

    k_gftt<<<tiles, blk>>>(imgs);
    k_topk<<<BB, 1024>>>();
    k_sparse<<<dim3(16, BB), 256>>>(scores);

    // join
    cudaStreamWaitEvent(0, g_hx.evJoin, 0);
    k_fin<<<1, 256>>>(out);
    (void)out_size;
}

// round 5
// speedup vs baseline: 1.1633x; 1.0003x over previous
#include <cuda_runtime.h>
#include <math.h>

#define BB 16
#define HH 512
#define WW 512
#define HWL (HH*WW)
#define NTOT (BB*HWL)
#define NCAND 4096
#define NTOP 500
#define NTILE 4096   // 16 imgs * 16 * 16 tiles

// ------------- device scratch (no allocations) -------------
__device__ float  g_cval[BB*NCAND];
__device__ int    g_cidx[BB*NCAND];
__device__ int    g_pts[BB*NTOP];
__device__ int    g_npt[BB];
__device__ double g_pA[NTILE];    // dense bce partials
__device__ double g_pB[NTILE];    // reg partials
__device__ double g_accS;         // sparse bce accumulator

// gaussian(7, sigma=1) normalized
__constant__ float GW[7] = {0.004433048f, 0.054005582f, 0.242036223f, 0.399050277f,
                            0.242036223f, 0.054005582f, 0.004433048f};

__device__ __forceinline__ int refl(int t, int n) {   // reflect101
    if (t < 0) t = -t;
    if (t >= n) t = 2 * n - 2 - t;
    return t;
}

// =====================================================================
// Kernel 1: fused gray -> sobel -> structure tensor -> gauss7 blur ->
//           GFTT response -> 5x5 NMS -> per-8x8-block argmax
// =====================================================================
__global__ void __launch_bounds__(1024) k_gftt(const float* __restrict__ imgs) {
    __shared__ float sm[11140];
    float* P0 = sm;                 // 1764
    float* P1 = sm + 1764;
    float* P2 = sm + 3528;          // ..5292
    float* GR = sm + 5292;          // 1936 (gray) — overwritten by BH later
    float* B0 = sm + 5292;          // 1512 each
    float* B1 = sm + 5292 + 1512;
    float* B2 = sm + 5292 + 3024;   // ..9828
    float* SS = sm + 9828;          // 1296 ..11124
    float* RM = sm;                 // rowmax 1152 (P dead by then)
    float* PVv = sm + 1152;         // 128
    int*   PIi = (int*)(sm + 1280); // 128

    int b  = blockIdx.z;
    int i0 = blockIdx.y * 32, j0 = blockIdx.x * 32;
    int tx = threadIdx.x, ty = threadIdx.y;
    int t  = ty * 32 + tx;
    if (b == 0 && blockIdx.x == 0 && blockIdx.y == 0 && t == 0) g_accS = 0.0;

    const float* img = imgs + (size_t)b * 3 * HWL;

    // --- gray 44x44 (clamped coords; covers replicate pad for sobel) ---
    for (int idx = t; idx < 44*44; idx += 1024) {
        int a = idx / 44, c = idx % 44;
        int gi = min(max(i0 - 6 + a, 0), HH - 1);
        int gj = min(max(j0 - 6 + c, 0), WW - 1);
        int p = gi * WW + gj;
        GR[idx] = 0.299f*img[p] + 0.587f*img[HWL+p] + 0.114f*img[2*HWL+p];
    }
    __syncthreads();

    // --- sobel products 42x42 at reflected coords ---
    for (int idx = t; idx < 42*42; idx += 1024) {
        int pr = idx / 42, pc = idx % 42;
        int r = refl(i0 - 5 + pr, HH);
        int c = refl(j0 - 5 + pc, WW);
        int rm_ = max(r-1,0)    - (i0-6), r0_ = r - (i0-6), rp_ = min(r+1,HH-1) - (i0-6);
        int cm_ = max(c-1,0)    - (j0-6), c0_ = c - (j0-6), cp_ = min(c+1,WW-1) - (j0-6);
        float A = GR[rm_*44+cm_], Bv = GR[rm_*44+c0_], C = GR[rm_*44+cp_];
        float D = GR[r0_*44+cm_],                      F = GR[r0_*44+cp_];
        float G = GR[rp_*44+cm_], H  = GR[rp_*44+c0_], K = GR[rp_*44+cp_];
        float dx = (C - A + 2.f*(F - D) + K - G) * 0.125f;
        float dy = (G - A + 2.f*(H - Bv) + K - C) * 0.125f;
        P0[idx] = dx*dx; P1[idx] = dy*dy; P2[idx] = dx*dy;
    }
    __syncthreads();

    // --- horizontal gauss7 : rows 42, cols 36 ---
    for (int idx = t; idx < 42*36; idx += 1024) {
        int r = idx / 36, cc = idx % 36;
        int base = r * 42 + cc;
        float s0 = 0.f, s1 = 0.f, s2 = 0.f;
#pragma unroll
        for (int k = 0; k < 7; k++) {
            float w = GW[k];
            s0 += w * P0[base + k];
            s1 += w * P1[base + k];
            s2 += w * P2[base + k];
        }
        B0[idx] = s0; B1[idx] = s1; B2[idx] = s2;
    }
    __syncthreads();

    // --- vertical gauss7 + response: S 36x36 ---
    for (int idx = t; idx < 36*36; idx += 1024) {
        int rr = idx / 36, cc = idx % 36;
        float a = 0.f, c = 0.f, e = 0.f;
#pragma unroll
        for (int k = 0; k < 7; k++) {
            float w = GW[k];
            int row = (rr + k) * 36 + cc;
            a += w * B0[row]; c += w * B1[row]; e += w * B2[row];
        }
        int gi = i0 - 2 + rr, gj = j0 - 2 + cc;
        float det = a * c - e * e, tr = a + c;
        float s = 0.5f * (tr - sqrtf(fabsf(tr*tr - 4.f*det)));
        SS[idx] = (gi >= 0 && gi < HH && gj >= 0 && gj < WW) ? s : -INFINITY;
    }
    __syncthreads();

    // --- 5x5 NMS (separable max) ---
    for (int idx = t; idx < 36*32; idx += 1024) {
        int r = idx / 32, c = idx % 32;
        float m = SS[r*36 + c];
#pragma unroll
        for (int k = 1; k < 5; k++) m = fmaxf(m, SS[r*36 + c + k]);
        RM[idx] = m;
    }
    __syncthreads();

    float s = SS[(ty+2)*36 + tx + 2];
    float m = RM[ty*32 + tx];
#pragma unroll
    for (int k = 1; k < 5; k++) m = fmaxf(m, RM[(ty+k)*32 + tx]);
    float v = (s == m) ? s : 0.f;
    int bi = (i0 + ty) * WW + (j0 + tx);
    float bv = v;
#pragma unroll
    for (int off = 4; off >= 1; off >>= 1) {
        float ov = __shfl_down_sync(0xffffffffu, bv, off, 8);
        int   oi = __shfl_down_sync(0xffffffffu, bi, off, 8);
        if (ov > bv || (ov == bv && oi < bi)) { bv = ov; bi = oi; }
    }
    if ((tx & 7) == 0) { PVv[ty*4 + (tx >> 3)] = bv; PIi[ty*4 + (tx >> 3)] = bi; }
    __syncthreads();
    if (t < 16) {
        int by = t >> 2, bx = t & 3;
        float mv = PVv[(by*8)*4 + bx]; int mi = PIi[(by*8)*4 + bx];
#pragma unroll
        for (int k = 1; k < 8; k++) {
            float pv = PVv[(by*8 + k)*4 + bx]; int pi2 = PIi[(by*8 + k)*4 + bx];
            if (pv > mv || (pv == mv && pi2 < mi)) { mv = pv; mi = pi2; }
        }
        int slot = b * NCAND + (blockIdx.y*4 + by) * 64 + (blockIdx.x*4 + bx);
        g_cval[slot] = mv; g_cidx[slot] = mi;
    }
}

// =====================================================================
// Kernel 2: per-image top-500 over 4096 candidates -> point list
// =====================================================================
__global__ void __launch_bounds__(1024) k_topk() {
    int b = blockIdx.x;
    __shared__ float sv[NCAND];
    __shared__ int cnt, firstGreater, eqcnt;
    __shared__ int eqidx[256];
    const float* cv = g_cval + b * NCAND;
    const int*   ci = g_cidx + b * NCAND;
    for (int t = threadIdx.x; t < NCAND; t += blockDim.x) sv[t] = cv[t];
    if (threadIdx.x == 0) { cnt = 0; firstGreater = NCAND; eqcnt = 0; }
    __syncthreads();
    for (int k = 2; k <= NCAND; k <<= 1)
        for (int j = k >> 1; j > 0; j >>= 1) {
            for (int t = threadIdx.x; t < NCAND; t += blockDim.x) {
                int ixj = t ^ j;
                if (ixj > t) {
                    bool up = ((t & k) == 0);
                    float A = sv[t], C = sv[ixj];
                    if ((A > C) == up) { sv[t] = C; sv[ixj] = A; }
                }
            }
            __syncthreads();
        }
    float thresh = sv[NCAND - NTOP];
    if (thresh > 0.f) {
        for (int t = threadIdx.x; t < NCAND; t += blockDim.x)
            if (sv[t] > thresh && (t == 0 || sv[t-1] <= thresh))
                atomicMin(&firstGreater, t);
        __syncthreads();
        int cgt = NCAND - firstGreater;
        for (int t = threadIdx.x; t < NCAND; t += blockDim.x) {
            float v = cv[t];
            if (v > thresh) {
                int p = atomicAdd(&cnt, 1);
                if (p < NTOP) g_pts[b*NTOP + p] = ci[t];
            } else if (v == thresh) {
                int p = atomicAdd(&eqcnt, 1);
                if (p < 256) eqidx[p] = ci[t];
            }
        }
        __syncthreads();
        if (threadIdx.x == 0) {
            int need = NTOP - cgt;
            int nn = min(eqcnt, 256);
            int base = min(cnt, NTOP);
            int added = 0;
            for (int s2 = 0; s2 < need && added < nn; s2++) {
                int best = -1, bi2 = 0x7fffffff;
                for (int q = 0; q < nn; q++)
                    if (eqidx[q] >= 0 && eqidx[q] < bi2) { bi2 = eqidx[q]; best = q; }
                if (best < 0) break;
                if (base + added < NTOP) g_pts[b*NTOP + base + added] = eqidx[best];
                eqidx[best] = -1;
                added++;
            }
            g_npt[b] = min(base + added, NTOP);
        }
    } else {
        for (int t = threadIdx.x; t < NCAND; t += blockDim.x)
            if (cv[t] > 0.f) {
                int p = atomicAdd(&cnt, 1);
                if (p < NTOP) g_pts[b*NTOP + p] = ci[t];
            }
        __syncthreads();
        if (threadIdx.x == 0) g_npt[b] = min(cnt, NTOP);
    }
}

// =====================================================================
// Kernel 3: dense part — sum(-log1mp) and reg = p*exp(-lap), tiled 32x32
// =====================================================================
__global__ void __launch_bounds__(1024) k_dense(const float* __restrict__ sc) {
    __shared__ float s[36*36];
    __shared__ float h[36*32];
    __shared__ double w1[32], w2[32];
    int b = blockIdx.z, i0 = blockIdx.y * 32, j0 = blockIdx.x * 32;
    int tx = threadIdx.x, ty = threadIdx.y, t = ty*32 + tx;
    const float* P = sc + (size_t)b * HWL;
    for (int idx = t; idx < 36*36; idx += 1024) {
        int a = idx / 36, c = idx % 36;
        s[idx] = P[refl(i0 - 2 + a, HH) * WW + refl(j0 - 2 + c, WW)];
    }
    __syncthreads();
    for (int idx = t; idx < 36*32; idx += 1024) {
        int r = idx / 32, c = idx % 32;
        float x = s[r*36 + c];
#pragma unroll
        for (int k = 1; k < 5; k++) x += s[r*36 + c + k];
        h[idx] = x;
    }
    __syncthreads();
    float p = s[(ty+2)*36 + tx + 2];
    float box = h[ty*32 + tx];
#pragma unroll
    for (int k = 1; k < 5; k++) box += h[(ty+k)*32 + tx];
    float lap = (box - 25.f * p) * (1.f / 48.f);
    double reg = (double)(p * expf(-lap));
    double bce = (double)(-fmaxf(log1pf(-p), -100.f));
    for (int off = 16; off; off >>= 1) {
        bce += __shfl_down_sync(0xffffffffu, bce, off);
        reg += __shfl_down_sync(0xffffffffu, reg, off);
    }
    if ((t & 31) == 0) { w1[t >> 5] = bce; w2[t >> 5] = reg; }
    __syncthreads();
    if (t < 32) {
        bce = w1[t]; reg = w2[t];
        for (int off = 16; off; off >>= 1) {
            bce += __shfl_down_sync(0xffffffffu, bce, off);
            reg += __shfl_down_sync(0xffffffffu, reg, off);
        }
        if (t == 0) {
            int tile = (b * 16 + blockIdx.y) * 16 + blockIdx.x;
            g_pA[tile] = bce; g_pB[tile] = reg;
        }
    }
}

// =====================================================================
// Kernel 4: sparse corner-BCE, parallel over (point, tap) pairs
//   contribution: wrow(kr)*wcol(kc) * (log1mp - logp) at (pi-3+kr, pj-3+kc)
// =====================================================================
__global__ void k_sparse(const float* __restrict__ sc) {
    int b = blockIdx.y;
    int n = g_npt[b];
    int total = n * 49;
    const float* P = sc + (size_t)b * HWL;
    double acc = 0.0;
    for (int w = blockIdx.x * blockDim.x + threadIdx.x; w < total;
         w += gridDim.x * blockDim.x) {
        int q = w / 49, tap = w % 49;
        int pix = g_pts[b*NTOP + q];
        int pi = pix / WW, pj = pix % WW;
        int kr = tap / 7, kc = tap % 7;
        int R = pi - 3 + kr, C = pj - 3 + kc;
        if (R < 0 || R >= HH || C < 0 || C >= WW) continue;
        // row weight: direct + reflect-folded (reflect101)
        float wrow = GW[kr];
        if (pi >= 1 && pi <= 3) {
            int d = -pi - R;                       // r+d = -pi (low reflection)
            if (d >= -3 && d <= 3) wrow += GW[d+3];
        }
        if (pi >= HH-4 && pi <= HH-2) {
            int d = 2*HH - 2 - pi - R;             // r+d = 2H-2-pi (high reflection)
            if (d >= -3 && d <= 3) wrow += GW[d+3];
        }
        float wcol = GW[kc];
        if (pj >= 1 && pj <= 3) {
            int d = -pj - C;
            if (d >= -3 && d <= 3) wcol += GW[d+3];
        }
        if (pj >= WW-4 && pj <= WW-2) {
            int d = 2*WW - 2 - pj - C;
            if (d >= -3 && d <= 3) wcol += GW[d+3];
        }
        float pv = P[R*WW + C];
        float lg = fmaxf(logf(pv), -100.f);
        float l1 = fmaxf(log1pf(-pv), -100.f);
        acc += (double)((wrow * wcol) * (l1 - lg));
    }
    __shared__ double wsum[8];
    int lane = threadIdx.x & 31, wid = threadIdx.x >> 5;
    for (int off = 16; off; off >>= 1) acc += __shfl_down_sync(0xffffffffu, acc, off);
    if (lane == 0) wsum[wid] = acc;
    __syncthreads();
    if (threadIdx.x == 0) {
        double s2 = 0;
        for (int k = 0; k < 8; k++) s2 += wsum[k];
        atomicAdd(&g_accS, s2);
    }
}

// =====================================================================
// Kernel 5: final reduce
// =====================================================================
__global__ void k_fin(float* __restrict__ out) {
    double a = 0, r = 0;
    for (int i = threadIdx.x; i < NTILE; i += blockDim.x) { a += g_pA[i]; r += g_pB[i]; }
    __shared__ double sa[256], sr[256];
    sa[threadIdx.x] = a; sr[threadIdx.x] = r;
    __syncthreads();
    for (int off = 128; off; off >>= 1) {
        if (threadIdx.x < off) { sa[threadIdx.x] += sa[threadIdx.x+off]; sr[threadIdx.x] += sr[threadIdx.x+off]; }
        __syncthreads();
    }
    if (threadIdx.x == 0)
        out[0] = (float)(((sa[0] + g_accS) + 10.0 * sr[0]) / (double)NTOT);
}

// ---------------- streams/events for fork-join overlap ----------------
struct HxStreams {
    cudaStream_t side;
    cudaEvent_t evFork, evJoin;
    HxStreams() {
        cudaStreamCreateWithFlags(&side, cudaStreamNonBlocking);
        cudaEventCreateWithFlags(&evFork, cudaEventDisableTiming);
        cudaEventCreateWithFlags(&evJoin, cudaEventDisableTiming);
    }
};
static HxStreams g_hx;

// =====================================================================
extern "C" void kernel_launch(void* const* d_in, const int* in_sizes, int n_in,
                              void* d_out, int out_size) {
    const float* scores = (const float*)d_in[0];
    const float* imgs   = (const float*)d_in[1];
    if (n_in >= 2 && in_sizes[0] > in_sizes[1]) {
        scores = (const float*)d_in[1];
        imgs   = (const float*)d_in[0];
    }
    float* out = (float*)d_out;

    dim3 tiles(16, 16, BB);
    dim3 blk(32, 32);

    // fork: dense pass runs concurrently with gftt->topk->sparse chain
    cudaEventRecord(g_hx.evFork, 0);
    cudaStreamWaitEvent(g_hx.side, g_hx.evFork, 0);
    k_dense<<<tiles, blk, 0, g_hx.side>>>(scores);
    cudaEventRecord(g_hx.evJoin, g_hx.side);

    k_gftt<<<tiles, blk>>>(imgs);
    k_topk<<<BB, 1024>>>();
    k_sparse<<<dim3(16, BB), 256>>>(scores);

    // join
    cudaStreamWaitEvent(0, g_hx.evJoin, 0);
    k_fin<<<1, 256>>>(out);
    (void)out_size;
}

// round 6
// speedup vs baseline: 1.2394x; 1.0654x over previous
#include <cuda_runtime.h>
#include <math.h>

#define BB 16
#define HH 512
#define WW 512
#define HWL (HH*WW)
#define NTOT (BB*HWL)
#define NCAND 4096
#define NTOP 500
#define NTILE 4096   // 16 imgs * 16*16 dense tiles

// ------------- device scratch (no allocations) -------------
__device__ float  g_cval[BB*NCAND];
__device__ int    g_cidx[BB*NCAND];
__device__ int    g_pts[BB*NTOP];
__device__ int    g_npt[BB];
__device__ double g_pA[NTILE];
__device__ double g_pB[NTILE];
__device__ double g_accS;

__constant__ float GW[7] = {0.004433048f, 0.054005582f, 0.242036223f, 0.399050277f,
                            0.242036223f, 0.054005582f, 0.004433048f};

__device__ __forceinline__ int refl(int t, int n) {   // reflect101
    if (t < 0) t = -t;
    if (t >= n) t = 2 * n - 2 - t;
    return t;
}

// =====================================================================
// Kernel 1: fused gray->sobel->structure tensor->gauss7->GFTT->NMS->
//           per-8x8-block argmax.  Tile: 32 wide x 64 tall, 1024 thr.
// smem layout (floats):
//   P0=0(3108) P1=3108 P2=6216        [74 x 42]
//   GR=9324(3344)                     [76 x 44]  (dead after sobel)
//   B0=9324 B1=11988 B2=14652        [74 x 36]  (overlays GR)
//   SS=17316(2448)                    [68 x 36]
//   RM=0(2176)                        [68 x 32]  (overlays P)
//   VV=2304(2048)                     [64 x 32]  (overlays P)
// total 19764 floats = 79056 B dynamic
// =====================================================================
__global__ void __launch_bounds__(1024, 2) k_gftt(const float* __restrict__ imgs) {
    extern __shared__ float sm[];
    float* P0 = sm;
    float* P1 = sm + 3108;
    float* P2 = sm + 6216;
    float* GR = sm + 9324;
    float* B0 = sm + 9324;
    float* B1 = sm + 11988;
    float* B2 = sm + 14652;
    float* SS = sm + 17316;
    float* RM = sm;
    float* VV = sm + 2304;

    int b  = blockIdx.z;
    int i0 = blockIdx.y * 64, j0 = blockIdx.x * 32;
    int t  = threadIdx.x;
    int tx = t & 31, tw = t >> 5;
    if (b == 0 && blockIdx.x == 0 && blockIdx.y == 0 && t == 0) g_accS = 0.0;

    const float* img = imgs + (size_t)b * 3 * HWL;

    // --- gray: 76 x 44 (clamped) ---
#pragma unroll
    for (int k = 0; k < 3; k++) {
        int r = tw + 32 * k;
        if (r < 76) {
            int gi = min(max(i0 - 6 + r, 0), HH - 1);
#pragma unroll
            for (int m = 0; m < 2; m++) {
                int c = tx + 32 * m;
                if (c < 44) {
                    int gj = min(max(j0 - 6 + c, 0), WW - 1);
                    int p = gi * WW + gj;
                    GR[r * 44 + c] = 0.299f * img[p] + 0.587f * img[HWL + p]
                                   + 0.114f * img[2 * HWL + p];
                }
            }
        }
    }
    __syncthreads();

    // --- sobel products: 74 x 42 at reflected coords ---
#pragma unroll
    for (int k = 0; k < 3; k++) {
        int r = tw + 32 * k;
        if (r < 74) {
            int rg = refl(i0 - 5 + r, HH);
            int rm_ = max(rg - 1, 0) - (i0 - 6);
            int r0_ = rg - (i0 - 6);
            int rp_ = min(rg + 1, HH - 1) - (i0 - 6);
#pragma unroll
            for (int m = 0; m < 2; m++) {
                int c = tx + 32 * m;
                if (c < 42) {
                    int cg = refl(j0 - 5 + c, WW);
                    int cm_ = max(cg - 1, 0) - (j0 - 6);
                    int c0_ = cg - (j0 - 6);
                    int cp_ = min(cg + 1, WW - 1) - (j0 - 6);
                    float A = GR[rm_*44+cm_], Bv = GR[rm_*44+c0_], C = GR[rm_*44+cp_];
                    float D = GR[r0_*44+cm_],                      F = GR[r0_*44+cp_];
                    float G = GR[rp_*44+cm_], H  = GR[rp_*44+c0_], K = GR[rp_*44+cp_];
                    float dx = (C - A + 2.f*(F - D) + K - G) * 0.125f;
                    float dy = (G - A + 2.f*(H - Bv) + K - C) * 0.125f;
                    int o = r * 42 + c;
                    P0[o] = dx * dx; P1[o] = dy * dy; P2[o] = dx * dy;
                }
            }
        }
    }
    __syncthreads();

    // --- horizontal gauss7: 74 x 36 ---
#pragma unroll
    for (int k = 0; k < 3; k++) {
        int r = tw + 32 * k;
        if (r < 74) {
#pragma unroll
            for (int m = 0; m < 2; m++) {
                int c = tx + 32 * m;
                if (c < 36) {
                    int base = r * 42 + c;
                    float s0 = 0.f, s1 = 0.f, s2 = 0.f;
#pragma unroll
                    for (int q = 0; q < 7; q++) {
                        float w = GW[q];
                        s0 += w * P0[base + q];
                        s1 += w * P1[base + q];
                        s2 += w * P2[base + q];
                    }
                    int o = r * 36 + c;
                    B0[o] = s0; B1[o] = s1; B2[o] = s2;
                }
            }
        }
    }
    __syncthreads();

    // --- vertical gauss7 + GFTT response: 68 x 36 ---
#pragma unroll
    for (int k = 0; k < 3; k++) {
        int r = tw + 32 * k;
        if (r < 68) {
            int gi = i0 - 2 + r;
#pragma unroll
            for (int m = 0; m < 2; m++) {
                int c = tx + 32 * m;
                if (c < 36) {
                    float a = 0.f, cc = 0.f, e = 0.f;
#pragma unroll
                    for (int q = 0; q < 7; q++) {
                        float w = GW[q];
                        int row = (r + q) * 36 + c;
                        a += w * B0[row]; cc += w * B1[row]; e += w * B2[row];
                    }
                    int gj = j0 - 2 + c;
                    float det = a * cc - e * e, tr = a + cc;
                    float s = 0.5f * (tr - sqrtf(fabsf(tr * tr - 4.f * det)));
                    SS[r * 36 + c] = (gi >= 0 && gi < HH && gj >= 0 && gj < WW)
                                   ? s : -INFINITY;
                }
            }
        }
    }
    __syncthreads();

    // --- NMS row-max: 68 x 32 ---
#pragma unroll
    for (int k = 0; k < 3; k++) {
        int r = tw + 32 * k;
        if (r < 68) {
            float mx = SS[r * 36 + tx];
#pragma unroll
            for (int q = 1; q < 5; q++) mx = fmaxf(mx, SS[r * 36 + tx + q]);
            RM[r * 32 + tx] = mx;
        }
    }
    __syncthreads();

    // --- per-pixel NMS value: 64 x 32 (2 per thread) ---
#pragma unroll
    for (int k = 0; k < 2; k++) {
        int r = tw + 32 * k;
        float s = SS[(r + 2) * 36 + tx + 2];
        float mx = RM[r * 32 + tx];
#pragma unroll
        for (int q = 1; q < 5; q++) mx = fmaxf(mx, RM[(r + q) * 32 + tx]);
        VV[r * 32 + tx] = (s == mx) ? s : 0.f;
    }
    __syncthreads();

    // --- 8x8 block argmax: 32 warps -> 32 blocks (8 rows x 4 cols) ---
    {
        int br = tw >> 2, bc = tw & 3;
        int e1 = tx, e2 = tx + 32;
        int r1 = br * 8 + (e1 >> 3), c1 = bc * 8 + (e1 & 7);
        int r2 = br * 8 + (e2 >> 3), c2 = bc * 8 + (e2 & 7);
        float v1 = VV[r1 * 32 + c1], v2 = VV[r2 * 32 + c2];
        int   i1 = (i0 + r1) * WW + (j0 + c1);
        int   i2 = (i0 + r2) * WW + (j0 + c2);
        float bv = v1; int bi = i1;
        if (v2 > bv) { bv = v2; bi = i2; }          // i1 < i2: keep i1 on tie
#pragma unroll
        for (int off = 16; off >= 1; off >>= 1) {
            float ov = __shfl_down_sync(0xffffffffu, bv, off);
            int   oi = __shfl_down_sync(0xffffffffu, bi, off);
            if (ov > bv || (ov == bv && oi < bi)) { bv = ov; bi = oi; }
        }
        if (tx == 0) {
            int cy = blockIdx.y * 8 + br;
            int cx = blockIdx.x * 4 + bc;
            int slot = b * NCAND + cy * 64 + cx;
            g_cval[slot] = bv; g_cidx[slot] = bi;
        }
    }
}

// =====================================================================
// Kernel 2: per-image top-500 via 4-round radix select (8-bit digits)
// =====================================================================
__global__ void __launch_bounds__(512) k_topk() {
    int b = blockIdx.x;
    const float* cv = g_cval + b * NCAND;
    const int*   ci = g_cidx + b * NCAND;
    __shared__ unsigned hist[256];
    __shared__ unsigned sh_prefix, sh_k, sh_cnt, sh_eqcnt;
    __shared__ int eqidx[256];

    unsigned u[8];
#pragma unroll
    for (int i = 0; i < 8; i++) {
        unsigned bits = __float_as_uint(cv[threadIdx.x + i * 512]);
        u[i] = bits ^ ((bits & 0x80000000u) ? 0xFFFFFFFFu : 0x80000000u);
    }
    if (threadIdx.x == 0) { sh_prefix = 0; sh_k = NTOP; sh_cnt = 0; sh_eqcnt = 0; }

    for (int shift = 24; shift >= 0; shift -= 8) {
        if (threadIdx.x < 256) hist[threadIdx.x] = 0;
        __syncthreads();
        unsigned pre = sh_prefix;
#pragma unroll
        for (int i = 0; i < 8; i++) {
            if (((unsigned long long)u[i] >> (shift + 8)) == (unsigned long long)pre)
                atomicAdd(&hist[(u[i] >> shift) & 255u], 1u);
        }
        __syncthreads();
        if (threadIdx.x == 0) {
            unsigned k = sh_k, cum = 0; int bin = 0;
            for (int q = 255; q >= 0; q--) {
                unsigned h = hist[q];
                if (cum + h >= k) { bin = q; break; }
                cum += h;
            }
            sh_k = k - cum;
            sh_prefix = (pre << 8) | (unsigned)bin;
        }
        __syncthreads();
    }

    unsigned uth = sh_prefix;
    int kneed = (int)sh_k;                         // ties of threshold still needed
    float thresh = (uth & 0x80000000u) ? __uint_as_float(uth ^ 0x80000000u)
                                       : __uint_as_float(~uth);

    if (thresh > 0.f) {
#pragma unroll
        for (int i = 0; i < 8; i++) {
            int idx = threadIdx.x + i * 512;
            if (u[i] > uth) {
                unsigned p = atomicAdd(&sh_cnt, 1u);
                if (p < NTOP) g_pts[b * NTOP + p] = ci[idx];
            } else if (u[i] == uth) {
                unsigned p = atomicAdd(&sh_eqcnt, 1u);
                if (p < 256) eqidx[p] = ci[idx];
            }
        }
        __syncthreads();
        if (threadIdx.x == 0) {
            int base = min((int)sh_cnt, NTOP);     // strictly-greater count
            int nn = min((int)sh_eqcnt, 256);
            int added = 0;
            while (added < kneed && added < nn) {
                int best = -1, bi2 = 0x7fffffff;
                for (int q = 0; q < nn; q++)
                    if (eqidx[q] >= 0 && eqidx[q] < bi2) { bi2 = eqidx[q]; best = q; }
                if (best < 0) break;
                if (base + added < NTOP) g_pts[b * NTOP + base + added] = bi2;
                eqidx[best] = -1;
                added++;
            }
            g_npt[b] = min(base + added, NTOP);
        }
    } else {
        const unsigned uzero = 0x80000000u;        // ordered form of +0.0
#pragma unroll
        for (int i = 0; i < 8; i++) {
            int idx = threadIdx.x + i * 512;
            if (u[i] > uzero) {
                unsigned p = atomicAdd(&sh_cnt, 1u);
                if (p < NTOP) g_pts[b * NTOP + p] = ci[idx];
            }
        }
        __syncthreads();
        if (threadIdx.x == 0) g_npt[b] = min((int)sh_cnt, NTOP);
    }
}

// =====================================================================
// Kernel 3: dense part — sum(-log1mp) and reg = p*exp(-lap), tiled 32x32
// =====================================================================
__global__ void __launch_bounds__(1024) k_dense(const float* __restrict__ sc) {
    __shared__ float s[36*36];
    __shared__ float h[36*32];
    __shared__ double w1[32], w2[32];
    int b = blockIdx.z, i0 = blockIdx.y * 32, j0 = blockIdx.x * 32;
    int tx = threadIdx.x, ty = threadIdx.y, t = ty*32 + tx;
    const float* P = sc + (size_t)b * HWL;
    for (int idx = t; idx < 36*36; idx += 1024) {
        int a = idx / 36, c = idx % 36;
        s[idx] = P[refl(i0 - 2 + a, HH) * WW + refl(j0 - 2 + c, WW)];
    }
    __syncthreads();
    for (int idx = t; idx < 36*32; idx += 1024) {
        int r = idx / 32, c = idx % 32;
        float x = s[r*36 + c];
#pragma unroll
        for (int k = 1; k < 5; k++) x += s[r*36 + c + k];
        h[idx] = x;
    }
    __syncthreads();
    float p = s[(ty+2)*36 + tx + 2];
    float box = h[ty*32 + tx];
#pragma unroll
    for (int k = 1; k < 5; k++) box += h[(ty+k)*32 + tx];
    float lap = (box - 25.f * p) * (1.f / 48.f);
    double reg = (double)(p * expf(-lap));
    double bce = (double)(-fmaxf(log1pf(-p), -100.f));
    for (int off = 16; off; off >>= 1) {
        bce += __shfl_down_sync(0xffffffffu, bce, off);
        reg += __shfl_down_sync(0xffffffffu, reg, off);
    }
    if ((t & 31) == 0) { w1[t >> 5] = bce; w2[t >> 5] = reg; }
    __syncthreads();
    if (t < 32) {
        bce = w1[t]; reg = w2[t];
        for (int off = 16; off; off >>= 1) {
            bce += __shfl_down_sync(0xffffffffu, bce, off);
            reg += __shfl_down_sync(0xffffffffu, reg, off);
        }
        if (t == 0) {
            int tile = (b * 16 + blockIdx.y) * 16 + blockIdx.x;
            g_pA[tile] = bce; g_pB[tile] = reg;
        }
    }
}

// =====================================================================
// Kernel 4: sparse corner-BCE over (point, tap) pairs
// =====================================================================
__global__ void k_sparse(const float* __restrict__ sc) {
    int b = blockIdx.y;
    int n = g_npt[b];
    int total = n * 49;
    const float* P = sc + (size_t)b * HWL;
    double acc = 0.0;
    for (int w = blockIdx.x * blockDim.x + threadIdx.x; w < total;
         w += gridDim.x * blockDim.x) {
        int q = w / 49, tap = w % 49;
        int pix = g_pts[b*NTOP + q];
        int pi = pix / WW, pj = pix % WW;
        int kr = tap / 7, kc = tap % 7;
        int R = pi - 3 + kr, C = pj - 3 + kc;
        if (R < 0 || R >= HH || C < 0 || C >= WW) continue;
        float wrow = GW[kr];
        if (pi >= 1 && pi <= 3) {
            int d = -pi - R;
            if (d >= -3 && d <= 3) wrow += GW[d+3];
        }
        if (pi >= HH-4 && pi <= HH-2) {
            int d = 2*HH - 2 - pi - R;
            if (d >= -3 && d <= 3) wrow += GW[d+3];
        }
        float wcol = GW[kc];
        if (pj >= 1 && pj <= 3) {
            int d = -pj - C;
            if (d >= -3 && d <= 3) wcol += GW[d+3];
        }
        if (pj >= WW-4 && pj <= WW-2) {
            int d = 2*WW - 2 - pj - C;
            if (d >= -3 && d <= 3) wcol += GW[d+3];
        }
        float pv = P[R*WW + C];
        float lg = fmaxf(logf(pv), -100.f);
        float l1 = fmaxf(log1pf(-pv), -100.f);
        acc += (double)((wrow * wcol) * (l1 - lg));
    }
    __shared__ double wsum[8];
    int lane = threadIdx.x & 31, wid = threadIdx.x >> 5;
    for (int off = 16; off; off >>= 1) acc += __shfl_down_sync(0xffffffffu, acc, off);
    if (lane == 0) wsum[wid] = acc;
    __syncthreads();
    if (threadIdx.x == 0) {
        double s2 = 0;
        for (int k = 0; k < 8; k++) s2 += wsum[k];
        atomicAdd(&g_accS, s2);
    }
}

// =====================================================================
// Kernel 5: final reduce
// =====================================================================
__global__ void k_fin(float* __restrict__ out) {
    double a = 0, r = 0;
    for (int i = threadIdx.x; i < NTILE; i += blockDim.x) { a += g_pA[i]; r += g_pB[i]; }
    __shared__ double sa[256], sr[256];
    sa[threadIdx.x] = a; sr[threadIdx.x] = r;
    __syncthreads();
    for (int off = 128; off; off >>= 1) {
        if (threadIdx.x < off) { sa[threadIdx.x] += sa[threadIdx.x+off]; sr[threadIdx.x] += sr[threadIdx.x+off]; }
        __syncthreads();
    }
    if (threadIdx.x == 0)
        out[0] = (float)(((sa[0] + g_accS) + 10.0 * sr[0]) / (double)NTOT);
}

// ---------------- streams/events for fork-join overlap ----------------
struct HxStreams {
    cudaStream_t side;
    cudaEvent_t evFork, evJoin;
    HxStreams() {
        cudaStreamCreateWithFlags(&side, cudaStreamNonBlocking);
        cudaEventCreateWithFlags(&evFork, cudaEventDisableTiming);
        cudaEventCreateWithFlags(&evJoin, cudaEventDisableTiming);
        cudaFuncSetAttribute(k_gftt, cudaFuncAttributeMaxDynamicSharedMemorySize,
                             19764 * sizeof(float));
    }
};
static HxStreams g_hx;

// =====================================================================
extern "C" void kernel_launch(void* const* d_in, const int* in_sizes, int n_in,
                              void* d_out, int out_size) {
    const float* scores = (const float*)d_in[0];
    const float* imgs   = (const float*)d_in[1];
    if (n_in >= 2 && in_sizes[0] > in_sizes[1]) {
        scores = (const float*)d_in[1];
        imgs   = (const float*)d_in[0];
    }
    float* out = (float*)d_out;

    // fork: dense pass runs concurrently with gftt->topk->sparse chain
    cudaEventRecord(g_hx.evFork, 0);
    cudaStreamWaitEvent(g_hx.side, g_hx.evFork, 0);
    k_dense<<<dim3(16, 16, BB), dim3(32, 32), 0, g_hx.side>>>(scores);
    cudaEventRecord(g_hx.evJoin, g_hx.side);

    k_gftt<<<dim3(16, 8, BB), 1024, 19764 * sizeof(float)>>>(imgs);
    k_topk<<<BB, 512>>>();
    k_sparse<<<dim3(64, BB), 256>>>(scores);

    // join
    cudaStreamWaitEvent(0, g_hx.evJoin, 0);
    k_fin<<<1, 256>>>(out);
    (void)out_size;
}

// round 7
// speedup vs baseline: 1.2888x; 1.0399x over previous
#include <cuda_runtime.h>
#include <math.h>

#define BB 16
#define HH 512
#define WW 512
#define HWL (HH*WW)
#define NTOT (BB*HWL)
#define NCAND 4096
#define NTOP 500
#define NTILE 4096   // 16 imgs * 16*16 dense tiles

// ------------- device scratch (no allocations) -------------
__device__ float  g_cval[BB*NCAND];
__device__ int    g_cidx[BB*NCAND];
__device__ int    g_pts[BB*NTOP];
__device__ int    g_npt[BB];
__device__ double g_pA[NTILE];
__device__ double g_pB[NTILE];
__device__ double g_accS;

__constant__ float GW[7] = {0.004433048f, 0.054005582f, 0.242036223f, 0.399050277f,
                            0.242036223f, 0.054005582f, 0.004433048f};

__device__ __forceinline__ int refl(int t, int n) {   // reflect101
    if (t < 0) t = -t;
    if (t >= n) t = 2 * n - 2 - t;
    return t;
}

// =====================================================================
// Kernel 1: fused gray->sobel->structure tensor->gauss7->GFTT->NMS->
//           per-8x8-block argmax.  32x32 tile, 256 threads, free regs.
// smem overlays (floats):
//   P0=0(1764) P1=1764 P2=3528 ..5292   [42x42]
//   GR=5292(1936)                        [44x44] (dead after sobel)
//   B0=5292 B1=6804 B2=8316 ..9828      [42x36] (overlay GR)
//   SS=9828(1296) ..11124                [36x36]
//   RM=0(1152)                           [36x32] (overlay P)
// =====================================================================
__global__ void __launch_bounds__(256) k_gftt(const float* __restrict__ imgs) {
    __shared__ float sm[11124];
    float* P0 = sm;
    float* P1 = sm + 1764;
    float* P2 = sm + 3528;
    float* GR = sm + 5292;
    float* B0 = sm + 5292;
    float* B1 = sm + 6804;
    float* B2 = sm + 8316;
    float* SS = sm + 9828;
    float* RM = sm;

    int b  = blockIdx.z;
    int i0 = blockIdx.y * 32, j0 = blockIdx.x * 32;
    int t  = threadIdx.x;
    int tx = t & 31, tw = t >> 5;
    if (b == 0 && blockIdx.x == 0 && blockIdx.y == 0 && t == 0) g_accS = 0.0;

    const float* img = imgs + (size_t)b * 3 * HWL;

    // --- gray: 44 x 44 (clamped coords) ---
    for (int r = tw; r < 44; r += 8) {
        int gi = min(max(i0 - 6 + r, 0), HH - 1);
        {
            int c = tx;
            int gj = min(max(j0 - 6 + c, 0), WW - 1);
            int p = gi * WW + gj;
            GR[r*44 + c] = 0.299f*img[p] + 0.587f*img[HWL+p] + 0.114f*img[2*HWL+p];
        }
        if (tx < 12) {
            int c = tx + 32;
            int gj = min(max(j0 - 6 + c, 0), WW - 1);
            int p = gi * WW + gj;
            GR[r*44 + c] = 0.299f*img[p] + 0.587f*img[HWL+p] + 0.114f*img[2*HWL+p];
        }
    }
    __syncthreads();

    // --- sobel products: 42 x 42 at reflected coords ---
    for (int r = tw; r < 42; r += 8) {
        int rg = refl(i0 - 5 + r, HH);
        int rm_ = max(rg - 1, 0) - (i0 - 6);
        int r0_ = rg - (i0 - 6);
        int rp_ = min(rg + 1, HH - 1) - (i0 - 6);
#pragma unroll
        for (int m = 0; m < 2; m++) {
            int c = tx + 32 * m;
            if (c < 42) {
                int cg = refl(j0 - 5 + c, WW);
                int cm_ = max(cg - 1, 0) - (j0 - 6);
                int c0_ = cg - (j0 - 6);
                int cp_ = min(cg + 1, WW - 1) - (j0 - 6);
                float A = GR[rm_*44+cm_], Bv = GR[rm_*44+c0_], C = GR[rm_*44+cp_];
                float D = GR[r0_*44+cm_],                      F = GR[r0_*44+cp_];
                float G = GR[rp_*44+cm_], H  = GR[rp_*44+c0_], K = GR[rp_*44+cp_];
                float dx = (C - A + 2.f*(F - D) + K - G) * 0.125f;
                float dy = (G - A + 2.f*(H - Bv) + K - C) * 0.125f;
                int o = r * 42 + c;
                P0[o] = dx * dx; P1[o] = dy * dy; P2[o] = dx * dy;
            }
        }
    }
    __syncthreads();

    // --- horizontal gauss7: 42 x 36 ---
    for (int r = tw; r < 42; r += 8) {
#pragma unroll
        for (int m = 0; m < 2; m++) {
            int c = tx + 32 * m;
            if (c < 36) {
                int base = r * 42 + c;
                float s0 = 0.f, s1 = 0.f, s2 = 0.f;
#pragma unroll
                for (int q = 0; q < 7; q++) {
                    float w = GW[q];
                    s0 += w * P0[base + q];
                    s1 += w * P1[base + q];
                    s2 += w * P2[base + q];
                }
                int o = r * 36 + c;
                B0[o] = s0; B1[o] = s1; B2[o] = s2;
            }
        }
    }
    __syncthreads();

    // --- vertical gauss7 + GFTT response: 36 x 36 ---
    for (int r = tw; r < 36; r += 8) {
        int gi = i0 - 2 + r;
#pragma unroll
        for (int m = 0; m < 2; m++) {
            int c = tx + 32 * m;
            if (c < 36) {
                float a = 0.f, cc = 0.f, e = 0.f;
#pragma unroll
                for (int q = 0; q < 7; q++) {
                    float w = GW[q];
                    int row = (r + q) * 36 + c;
                    a += w * B0[row]; cc += w * B1[row]; e += w * B2[row];
                }
                int gj = j0 - 2 + c;
                float det = a * cc - e * e, tr = a + cc;
                float s = 0.5f * (tr - sqrtf(fabsf(tr * tr - 4.f * det)));
                SS[r * 36 + c] = (gi >= 0 && gi < HH && gj >= 0 && gj < WW)
                               ? s : -INFINITY;
            }
        }
    }
    __syncthreads();

    // --- NMS row-max: 36 x 32 ---
    for (int r = tw; r < 36; r += 8) {
        float mx = SS[r * 36 + tx];
#pragma unroll
        for (int q = 1; q < 5; q++) mx = fmaxf(mx, SS[r * 36 + tx + q]);
        RM[r * 32 + tx] = mx;
    }
    __syncthreads();

    // --- per-pixel NMS + 8x8 block argmax: warp tw handles blocks 2tw, 2tw+1 ---
#pragma unroll
    for (int k = 0; k < 2; k++) {
        int bb = 2 * tw + k;
        int br = bb >> 2, bc = bb & 3;
        float bv = -1.f; int bi = 0x7fffffff;
#pragma unroll
        for (int h = 0; h < 2; h++) {
            int e = tx + 32 * h;
            int r = br * 8 + (e >> 3), c = bc * 8 + (e & 7);
            float s = SS[(r + 2) * 36 + c + 2];
            float mx = RM[r * 32 + c];
#pragma unroll
            for (int q = 1; q < 5; q++) mx = fmaxf(mx, RM[(r + q) * 32 + c]);
            float v = (s == mx) ? s : 0.f;
            int gix = (i0 + r) * WW + (j0 + c);
            if (v > bv || (v == bv && gix < bi)) { bv = v; bi = gix; }
        }
#pragma unroll
        for (int off = 16; off >= 1; off >>= 1) {
            float ov = __shfl_down_sync(0xffffffffu, bv, off);
            int   oi = __shfl_down_sync(0xffffffffu, bi, off);
            if (ov > bv || (ov == bv && oi < bi)) { bv = ov; bi = oi; }
        }
        if (tx == 0) {
            int cy = blockIdx.y * 4 + br;
            int cx = blockIdx.x * 4 + bc;
            g_cval[b * NCAND + cy * 64 + cx] = bv;
            g_cidx[b * NCAND + cy * 64 + cx] = bi;
        }
    }
}

// =====================================================================
// Kernel 2: per-image top-500 via 4-round radix select, parallel scan
// =====================================================================
__global__ void __launch_bounds__(512) k_topk() {
    int b = blockIdx.x;
    const float* cv = g_cval + b * NCAND;
    const int*   ci = g_cidx + b * NCAND;
    __shared__ unsigned hist[256];
    __shared__ unsigned scan[256];
    __shared__ unsigned sh_prefix, sh_k, sh_cnt, sh_eqcnt;
    __shared__ int eqidx[256];

    unsigned u[8];
#pragma unroll
    for (int i = 0; i < 8; i++) {
        unsigned bits = __float_as_uint(cv[threadIdx.x + i * 512]);
        u[i] = bits ^ ((bits & 0x80000000u) ? 0xFFFFFFFFu : 0x80000000u);
    }
    if (threadIdx.x == 0) { sh_prefix = 0; sh_k = NTOP; sh_cnt = 0; sh_eqcnt = 0; }

    for (int shift = 24; shift >= 0; shift -= 8) {
        if (threadIdx.x < 256) hist[threadIdx.x] = 0;
        __syncthreads();
        unsigned pre = sh_prefix;
#pragma unroll
        for (int i = 0; i < 8; i++) {
            if (((unsigned long long)u[i] >> (shift + 8)) == (unsigned long long)pre)
                atomicAdd(&hist[(u[i] >> shift) & 255u], 1u);
        }
        __syncthreads();
        // suffix sums S(q) = sum_{i>=q} hist[i], Hillis-Steele
        if (threadIdx.x < 256) scan[threadIdx.x] = hist[threadIdx.x];
        __syncthreads();
        for (int off = 1; off < 256; off <<= 1) {
            unsigned add = 0;
            if (threadIdx.x < 256 && threadIdx.x + off < 256)
                add = scan[threadIdx.x + off];
            __syncthreads();
            if (threadIdx.x < 256) scan[threadIdx.x] += add;
            __syncthreads();
        }
        if (threadIdx.x < 256) {
            unsigned k = sh_k;
            unsigned Sq  = scan[threadIdx.x];
            unsigned Sq1 = (threadIdx.x == 255) ? 0u : scan[threadIdx.x + 1];
            if (Sq >= k && Sq1 < k) {               // exactly one thread
                sh_k = k - Sq1;
                sh_prefix = (pre << 8) | (unsigned)threadIdx.x;
            }
        }
        __syncthreads();
    }

    unsigned uth = sh_prefix;
    int kneed = (int)sh_k;
    float thresh = (uth & 0x80000000u) ? __uint_as_float(uth ^ 0x80000000u)
                                       : __uint_as_float(~uth);

    if (thresh > 0.f) {
#pragma unroll
        for (int i = 0; i < 8; i++) {
            int idx = threadIdx.x + i * 512;
            if (u[i] > uth) {
                unsigned p = atomicAdd(&sh_cnt, 1u);
                if (p < NTOP) g_pts[b * NTOP + p] = ci[idx];
            } else if (u[i] == uth) {
                unsigned p = atomicAdd(&sh_eqcnt, 1u);
                if (p < 256) eqidx[p] = ci[idx];
            }
        }
        __syncthreads();
        if (threadIdx.x == 0) {
            int base = min((int)sh_cnt, NTOP);
            int nn = min((int)sh_eqcnt, 256);
            int added = 0;
            while (added < kneed && added < nn) {
                int best = -1, bi2 = 0x7fffffff;
                for (int q = 0; q < nn; q++)
                    if (eqidx[q] >= 0 && eqidx[q] < bi2) { bi2 = eqidx[q]; best = q; }
                if (best < 0) break;
                if (base + added < NTOP) g_pts[b * NTOP + base + added] = bi2;
                eqidx[best] = -1;
                added++;
            }
            g_npt[b] = min(base + added, NTOP);
        }
    } else {
        const unsigned uzero = 0x80000000u;
#pragma unroll
        for (int i = 0; i < 8; i++) {
            int idx = threadIdx.x + i * 512;
            if (u[i] > uzero) {
                unsigned p = atomicAdd(&sh_cnt, 1u);
                if (p < NTOP) g_pts[b * NTOP + p] = ci[idx];
            }
        }
        __syncthreads();
        if (threadIdx.x == 0) g_npt[b] = min((int)sh_cnt, NTOP);
    }
}

// =====================================================================
// Kernel 3: dense part — sum(-log1mp) and reg = p*exp(-lap), tiled 32x32
// =====================================================================
__global__ void __launch_bounds__(1024) k_dense(const float* __restrict__ sc) {
    __shared__ float s[36*36];
    __shared__ float h[36*32];
    __shared__ double w1[32], w2[32];
    int b = blockIdx.z, i0 = blockIdx.y * 32, j0 = blockIdx.x * 32;
    int tx = threadIdx.x, ty = threadIdx.y, t = ty*32 + tx;
    const float* P = sc + (size_t)b * HWL;
    for (int idx = t; idx < 36*36; idx += 1024) {
        int a = idx / 36, c = idx % 36;
        s[idx] = P[refl(i0 - 2 + a, HH) * WW + refl(j0 - 2 + c, WW)];
    }
    __syncthreads();
    for (int idx = t; idx < 36*32; idx += 1024) {
        int r = idx / 32, c = idx % 32;
        float x = s[r*36 + c];
#pragma unroll
        for (int k = 1; k < 5; k++) x += s[r*36 + c + k];
        h[idx] = x;
    }
    __syncthreads();
    float p = s[(ty+2)*36 + tx + 2];
    float box = h[ty*32 + tx];
#pragma unroll
    for (int k = 1; k < 5; k++) box += h[(ty+k)*32 + tx];
    float lap = (box - 25.f * p) * (1.f / 48.f);
    double reg = (double)(p * expf(-lap));
    double bce = (double)(-fmaxf(log1pf(-p), -100.f));
    for (int off = 16; off; off >>= 1) {
        bce += __shfl_down_sync(0xffffffffu, bce, off);
        reg += __shfl_down_sync(0xffffffffu, reg, off);
    }
    if ((t & 31) == 0) { w1[t >> 5] = bce; w2[t >> 5] = reg; }
    __syncthreads();
    if (t < 32) {
        bce = w1[t]; reg = w2[t];
        for (int off = 16; off; off >>= 1) {
            bce += __shfl_down_sync(0xffffffffu, bce, off);
            reg += __shfl_down_sync(0xffffffffu, reg, off);
        }
        if (t == 0) {
            int tile = (b * 16 + blockIdx.y) * 16 + blockIdx.x;
            g_pA[tile] = bce; g_pB[tile] = reg;
        }
    }
}

// =====================================================================
// Kernel 4: sparse corner-BCE, taps padded to 64 (no div; warp=point)
// =====================================================================
__global__ void k_sparse(const float* __restrict__ sc) {
    int b = blockIdx.y;
    int n = g_npt[b];
    int total = n * 64;
    const float* P = sc + (size_t)b * HWL;
    double acc = 0.0;
    for (int w = blockIdx.x * blockDim.x + threadIdx.x; w < total;
         w += gridDim.x * blockDim.x) {
        int q = w >> 6, tap = w & 63;
        if (tap >= 49) continue;
        int pix = g_pts[b*NTOP + q];
        int pi = pix >> 9, pj = pix & 511;           // WW = 512
        int kr = tap / 7, kc = tap - kr * 7;
        int R = pi - 3 + kr, C = pj - 3 + kc;
        if (R < 0 || R >= HH || C < 0 || C >= WW) continue;
        float wrow = GW[kr];
        if (pi >= 1 && pi <= 3) {
            int d = -pi - R;
            if (d >= -3 && d <= 3) wrow += GW[d+3];
        }
        if (pi >= HH-4 && pi <= HH-2) {
            int d = 2*HH - 2 - pi - R;
            if (d >= -3 && d <= 3) wrow += GW[d+3];
        }
        float wcol = GW[kc];
        if (pj >= 1 && pj <= 3) {
            int d = -pj - C;
            if (d >= -3 && d <= 3) wcol += GW[d+3];
        }
        if (pj >= WW-4 && pj <= WW-2) {
            int d = 2*WW - 2 - pj - C;
            if (d >= -3 && d <= 3) wcol += GW[d+3];
        }
        float pv = P[R*WW + C];
        float lg = fmaxf(logf(pv), -100.f);
        float l1 = fmaxf(log1pf(-pv), -100.f);
        acc += (double)((wrow * wcol) * (l1 - lg));
    }
    __shared__ double wsum[8];
    int lane = threadIdx.x & 31, wid = threadIdx.x >> 5;
    for (int off = 16; off; off >>= 1) acc += __shfl_down_sync(0xffffffffu, acc, off);
    if (lane == 0) wsum[wid] = acc;
    __syncthreads();
    if (threadIdx.x == 0) {
        double s2 = 0;
        for (int k = 0; k < 8; k++) s2 += wsum[k];
        atomicAdd(&g_accS, s2);
    }
}

// =====================================================================
// Kernel 5: final reduce
// =====================================================================
__global__ void k_fin(float* __restrict__ out) {
    double a = 0, r = 0;
    for (int i = threadIdx.x; i < NTILE; i += blockDim.x) { a += g_pA[i]; r += g_pB[i]; }
    __shared__ double sa[256], sr[256];
    sa[threadIdx.x] = a; sr[threadIdx.x] = r;
    __syncthreads();
    for (int off = 128; off; off >>= 1) {
        if (threadIdx.x < off) { sa[threadIdx.x] += sa[threadIdx.x+off]; sr[threadIdx.x] += sr[threadIdx.x+off]; }
        __syncthreads();
    }
    if (threadIdx.x == 0)
        out[0] = (float)(((sa[0] + g_accS) + 10.0 * sr[0]) / (double)NTOT);
}

// ---------------- streams/events for fork-join overlap ----------------
struct HxStreams {
    cudaStream_t side;
    cudaEvent_t evFork, evJoin;
    HxStreams() {
        cudaStreamCreateWithFlags(&side, cudaStreamNonBlocking);
        cudaEventCreateWithFlags(&evFork, cudaEventDisableTiming);
        cudaEventCreateWithFlags(&evJoin, cudaEventDisableTiming);
    }
};
static HxStreams g_hx;

// =====================================================================
extern "C" void kernel_launch(void* const* d_in, const int* in_sizes, int n_in,
                              void* d_out, int out_size) {
    const float* scores = (const float*)d_in[0];
    const float* imgs   = (const float*)d_in[1];
    if (n_in >= 2 && in_sizes[0] > in_sizes[1]) {
        scores = (const float*)d_in[1];
        imgs   = (const float*)d_in[0];
    }
    float* out = (float*)d_out;

    // fork: dense pass runs concurrently with gftt->topk->sparse chain
    cudaEventRecord(g_hx.evFork, 0);
    cudaStreamWaitEvent(g_hx.side, g_hx.evFork, 0);
    k_dense<<<dim3(16, 16, BB), dim3(32, 32), 0, g_hx.side>>>(scores);
    cudaEventRecord(g_hx.evJoin, g_hx.side);

    k_gftt<<<dim3(16, 16, BB), 256>>>(imgs);
    k_topk<<<BB, 512>>>();
    k_sparse<<<dim3(128, BB), 256>>>(scores);

    // join
    cudaStreamWaitEvent(0, g_hx.evJoin, 0);
    k_fin<<<1, 256>>>(out);
    (void)out_size;
}